// round 1
// baseline (speedup 1.0000x reference)
#include <cuda_runtime.h>
#include <cuda_bf16.h>

// Problem constants (fixed by the reference)
#define NB    16
#define LSEQ  2048
#define NNODE (NB * LSEQ)      // 32768
#define DIN   128
#define DHID  256
#define DOUT  128

// Scratch (device globals; no allocation allowed)
__device__ float g_Y [NNODE * (2 * DHID)];   // [N, 512] rel|root GEMM output (reused L1/L2)
__device__ float g_H1[NNODE * DHID];         // [N, 256]
__device__ float g_H2[NNODE * DHID];         // [N, 256]
__device__ float g_B1[(2 * DHID) * DIN];     // [512, 128] = stack(W_rel1, W_root1)
__device__ float g_B2[(2 * DHID) * DHID];    // [512, 256] = stack(W_rel2, W_root2)

// ---------------------------------------------------------------------------
// GEMM: C[M,Nn] = A[M,K] @ B[Nn,K]^T (+ bias per column, optional)
// Row-major A and B (B is the weight matrix [out, in], i.e. K-contiguous).
// Tile: 128x128, BK=16, 256 threads, 8x8 per-thread micro-tile.
// M % 128 == 0, Nn % 128 == 0, K % 16 == 0 guaranteed by problem shapes.
// ---------------------------------------------------------------------------
__global__ __launch_bounds__(256, 2)
void gemm_nt(const float* __restrict__ A, const float* __restrict__ B,
             float* __restrict__ C, const float* __restrict__ bias,
             int M, int Nn, int K)
{
    __shared__ float As[16][128];
    __shared__ float Bs[16][128];

    const int tid  = threadIdx.x;
    const int bm   = blockIdx.y * 128;
    const int bn   = blockIdx.x * 128;
    const int tcol = tid & 15;   // 0..15
    const int trow = tid >> 4;   // 0..15

    float acc[8][8];
#pragma unroll
    for (int i = 0; i < 8; ++i)
#pragma unroll
        for (int j = 0; j < 8; ++j) acc[i][j] = 0.0f;

    for (int k0 = 0; k0 < K; k0 += 16) {
        // Load 128x16 A-tile and 128x16 B-tile (512 float4 each, 2 per thread)
#pragma unroll
        for (int t = 0; t < 2; ++t) {
            const int f  = tid + t * 256;       // 0..511
            const int r  = f >> 2;              // row in tile 0..127
            const int kc = (f & 3) << 2;        // k offset 0,4,8,12
            float4 va = *(const float4*)(A + (size_t)(bm + r) * K + k0 + kc);
            As[kc + 0][r] = va.x; As[kc + 1][r] = va.y;
            As[kc + 2][r] = va.z; As[kc + 3][r] = va.w;
            float4 vb = *(const float4*)(B + (size_t)(bn + r) * K + k0 + kc);
            Bs[kc + 0][r] = vb.x; Bs[kc + 1][r] = vb.y;
            Bs[kc + 2][r] = vb.z; Bs[kc + 3][r] = vb.w;
        }
        __syncthreads();

#pragma unroll
        for (int kk = 0; kk < 16; ++kk) {
            float4 a0 = *(const float4*)&As[kk][trow * 8 + 0];
            float4 a1 = *(const float4*)&As[kk][trow * 8 + 4];
            float4 b0 = *(const float4*)&Bs[kk][tcol * 8 + 0];
            float4 b1 = *(const float4*)&Bs[kk][tcol * 8 + 4];
            const float ra[8] = {a0.x, a0.y, a0.z, a0.w, a1.x, a1.y, a1.z, a1.w};
            const float rb[8] = {b0.x, b0.y, b0.z, b0.w, b1.x, b1.y, b1.z, b1.w};
#pragma unroll
            for (int i = 0; i < 8; ++i)
#pragma unroll
                for (int j = 0; j < 8; ++j)
                    acc[i][j] = fmaf(ra[i], rb[j], acc[i][j]);
        }
        __syncthreads();
    }

    // Epilogue: optional per-column bias, then store (2 float4 per row)
    float bv[8];
#pragma unroll
    for (int j = 0; j < 8; ++j)
        bv[j] = bias ? __ldg(&bias[bn + tcol * 8 + j]) : 0.0f;

#pragma unroll
    for (int i = 0; i < 8; ++i) {
        float* crow = C + (size_t)(bm + trow * 8 + i) * Nn + bn + tcol * 8;
        float4 o0 = make_float4(acc[i][0] + bv[0], acc[i][1] + bv[1],
                                acc[i][2] + bv[2], acc[i][3] + bv[3]);
        float4 o1 = make_float4(acc[i][4] + bv[4], acc[i][5] + bv[5],
                                acc[i][6] + bv[6], acc[i][7] + bv[7]);
        *(float4*)(crow + 0) = o0;
        *(float4*)(crow + 4) = o1;
    }
}

// ---------------------------------------------------------------------------
// Layer epilogue: H[i,j] = PReLU( sum_{d=1..8, t>=d} w_d * Y[i-d, j]
//                                 + Y[i, 256+j] + bias[j] , a )
// Y is [N, 512] (cols 0:256 = h@W_rel^T, cols 256:512 = h@W_root^T).
// Window weights w_d read from edge_attr block starts (constant per offset).
// One thread = 4 consecutive columns of one row.
// ---------------------------------------------------------------------------
__global__ void layer_epilogue(const float* __restrict__ Y,
                               const float* __restrict__ bias,
                               const float* __restrict__ edge_attr,
                               const float* __restrict__ aslope,
                               float* __restrict__ H)
{
    const int idx = blockIdx.x * blockDim.x + threadIdx.x;   // 0 .. N*64
    const int row = idx >> 6;
    const int c4  = idx & 63;            // float4 column index (col = c4*4)
    const int t   = row & (LSEQ - 1);    // position within sequence

    // per-offset edge weights: start index of each d-block in edge_attr
    const int starts[8] = {0, 2047, 4093, 6138, 8182, 10225, 12267, 14308};
    float w[8];
#pragma unroll
    for (int d = 0; d < 8; ++d) w[d] = __ldg(&edge_attr[starts[d]]);

    const float4* Yv = (const float4*)Y;       // row stride = 128 float4
    float4 v = Yv[(size_t)row * 128 + 64 + c4];        // root part
    float4 b = *(const float4*)&bias[c4 * 4];
    v.x += b.x; v.y += b.y; v.z += b.z; v.w += b.w;

#pragma unroll
    for (int d = 1; d <= 8; ++d) {
        if (t >= d) {
            float4 r = Yv[(size_t)(row - d) * 128 + c4];  // rel part, shifted
            const float wd = w[d - 1];
            v.x = fmaf(wd, r.x, v.x);
            v.y = fmaf(wd, r.y, v.y);
            v.z = fmaf(wd, r.z, v.z);
            v.w = fmaf(wd, r.w, v.w);
        }
    }

    const float a = __ldg(aslope);
    v.x = v.x >= 0.0f ? v.x : a * v.x;
    v.y = v.y >= 0.0f ? v.y : a * v.y;
    v.z = v.z >= 0.0f ? v.z : a * v.z;
    v.w = v.w >= 0.0f ? v.w : a * v.w;

    *(float4*)&H[(size_t)row * DHID + c4 * 4] = v;
}

// ---------------------------------------------------------------------------
extern "C" void kernel_launch(void* const* d_in, const int* in_sizes, int n_in,
                              void* d_out, int out_size)
{
    const float* X       = (const float*)d_in[0];   // [16,2048,128]
    const float* W_rel1  = (const float*)d_in[1];   // [256,128]
    const float* b_rel1  = (const float*)d_in[2];   // [256]
    const float* W_root1 = (const float*)d_in[3];   // [256,128]
    const float* W_rel2  = (const float*)d_in[4];   // [256,256]
    const float* b_rel2  = (const float*)d_in[5];   // [256]
    const float* W_root2 = (const float*)d_in[6];   // [256,256]
    const float* a1      = (const float*)d_in[7];   // [1]
    const float* a2      = (const float*)d_in[8];   // [1]
    const float* W_fc    = (const float*)d_in[9];   // [128,256]
    const float* b_fc    = (const float*)d_in[10];  // [128]
    const float* ea      = (const float*)d_in[11];  // [E]
    float*       out     = (float*)d_out;           // [32768,128]

    float *Y, *H1, *H2, *B1, *B2;
    cudaGetSymbolAddress((void**)&Y,  g_Y);
    cudaGetSymbolAddress((void**)&H1, g_H1);
    cudaGetSymbolAddress((void**)&H2, g_H2);
    cudaGetSymbolAddress((void**)&B1, g_B1);
    cudaGetSymbolAddress((void**)&B2, g_B2);

    // Stack weights: B1 = [W_rel1 ; W_root1], B2 = [W_rel2 ; W_root2]
    cudaMemcpyAsync(B1,                W_rel1,  DHID * DIN  * sizeof(float), cudaMemcpyDeviceToDevice);
    cudaMemcpyAsync(B1 + DHID * DIN,   W_root1, DHID * DIN  * sizeof(float), cudaMemcpyDeviceToDevice);
    cudaMemcpyAsync(B2,                W_rel2,  DHID * DHID * sizeof(float), cudaMemcpyDeviceToDevice);
    cudaMemcpyAsync(B2 + DHID * DHID,  W_root2, DHID * DHID * sizeof(float), cudaMemcpyDeviceToDevice);

    const int epi_blocks = (NNODE * (DHID / 4)) / 256;   // 8192

    // Layer 1: Y = X @ [W_rel1;W_root1]^T  -> epilogue -> H1
    {
        dim3 grid(2 * DHID / 128, NNODE / 128);          // (4, 256)
        gemm_nt<<<grid, 256>>>(X, B1, Y, nullptr, NNODE, 2 * DHID, DIN);
        layer_epilogue<<<epi_blocks, 256>>>(Y, b_rel1, ea, a1, H1);
    }
    // Layer 2: Y = H1 @ [W_rel2;W_root2]^T -> epilogue -> H2
    {
        dim3 grid(2 * DHID / 128, NNODE / 128);          // (4, 256)
        gemm_nt<<<grid, 256>>>(H1, B2, Y, nullptr, NNODE, 2 * DHID, DHID);
        layer_epilogue<<<epi_blocks, 256>>>(Y, b_rel2, ea, a2, H2);
    }
    // FC: out = H2 @ W_fc^T + b_fc
    {
        dim3 grid(DOUT / 128, NNODE / 128);              // (1, 256)
        gemm_nt<<<grid, 256>>>(H2, W_fc, out, b_fc, NNODE, DOUT, DHID);
    }
}

// round 3
// speedup vs baseline: 1.8525x; 1.8525x over previous
#include <cuda_runtime.h>
#include <cuda_bf16.h>
#include <cstdint>

#define NNODE 32768
#define LSEQ  2048

// ---------------- device scratch (no allocation allowed) -------------------
__device__ __align__(16) __nv_bfloat16 g_A1[NNODE * 256];   // [N, 2*128]  X hi|lo
__device__ __align__(16) __nv_bfloat16 g_A2[NNODE * 512];   // [N, 2*256]  H hi|lo (reused)
__device__ __align__(16) float         g_Y [NNODE * 512];   // [N, 512] rel|root fp32
__device__ __align__(16) __nv_bfloat16 g_B1[512 * 256];     // [512, 2*128]
__device__ __align__(16) __nv_bfloat16 g_B2[512 * 512];     // [512, 2*256]
__device__ __align__(16) __nv_bfloat16 g_Bf[128 * 512];     // [128, 2*256]

// ---------------- PTX helpers ----------------------------------------------
static __device__ __forceinline__ void cp16(uint32_t dst, const void* src) {
    asm volatile("cp.async.cg.shared.global [%0], [%1], 16;" :: "r"(dst), "l"(src) : "memory");
}
static __device__ __forceinline__ void cp_commit() {
    asm volatile("cp.async.commit_group;" ::: "memory");
}

#define LDSM4(r0, r1, r2, r3, a) \
    asm volatile("ldmatrix.sync.aligned.m8n8.x4.shared.b16 {%0,%1,%2,%3}, [%4];" \
                 : "=r"(r0), "=r"(r1), "=r"(r2), "=r"(r3) : "r"(a))

#define MMA16816(d, a, b0, b1) \
    asm volatile("mma.sync.aligned.m16n8k16.row.col.f32.bf16.bf16.f32 " \
                 "{%0,%1,%2,%3}, {%4,%5,%6,%7}, {%8,%9}, {%0,%1,%2,%3};" \
                 : "+f"((d)[0]), "+f"((d)[1]), "+f"((d)[2]), "+f"((d)[3]) \
                 : "r"((a)[0]), "r"((a)[1]), "r"((a)[2]), "r"((a)[3]), \
                   "r"(b0), "r"(b1))

// ---------------------------------------------------------------------------
// Split-K3 bf16 HMMA GEMM (mma.sync m16n8k16).
// A' [M, 2*KK] = [Ah|Al], B' [Nn, 2*KK] = [Bh|Bl], K-major bf16.
// C = Ah@Bh^T + Ah@Bl^T + Al@Bh^T (fp32 accum), virtual K = 3*KK.
// CTA tile 128x128, BK=32, 8 warps (4M x 2N), warp tile 32x64.
// Smem rows: 32 bf16 = 64B data at 80B stride (bank-conflict-free ldmatrix).
// ---------------------------------------------------------------------------
#define ROWB   80
#define TILEB  (128 * ROWB)          // 10240 per operand tile
#define STAGEB (2 * TILEB)           // 20480 per stage

template <bool BIAS>
__global__ __launch_bounds__(256)
void gemm_mma(const __nv_bfloat16* __restrict__ A, const __nv_bfloat16* __restrict__ B,
              float* __restrict__ C, const float* __restrict__ bias, int KK, int Nn)
{
    __shared__ __align__(16) char smem[2 * STAGEB];   // 40960 B
    const uint32_t sb = (uint32_t)__cvta_generic_to_shared(smem);

    const int tid    = threadIdx.x;
    const int lane   = tid & 31;
    const int wid    = tid >> 5;
    const int warp_m = wid & 3;          // 0..3 -> 32-row block
    const int warp_n = wid >> 2;         // 0..1 -> 64-col block
    const int bm     = blockIdx.y * 128;
    const int bn     = blockIdx.x * 128;
    const int lda    = 2 * KK;
    const int nkk    = KK >> 5;          // 32-elem chunks per segment
    const int nc     = 3 * nkk;

    // ---- cp.async source/dest (chunk-invariant parts); 2 units per thread --
    const __nv_bfloat16* asrc[2]; uint32_t adst[2];
    const __nv_bfloat16* bsrc[2]; uint32_t bdst[2];
#pragma unroll
    for (int i = 0; i < 2; ++i) {
        int u = i * 256 + tid, r = u >> 2, q = u & 3;
        asrc[i] = A + (size_t)(bm + r) * lda + q * 8;
        adst[i] = sb + (uint32_t)(r * ROWB + q * 16);
        bsrc[i] = B + (size_t)(bn + r) * lda + q * 8;
        bdst[i] = sb + TILEB + (uint32_t)(r * ROWB + q * 16);
    }

    auto issue = [&](int c) {
        int seg = c / nkk, r0 = c - seg * nkk;
        int ka  = ((seg == 2) ? nkk : 0) + r0;   // Ah, Ah, Al
        int kb  = ((seg == 1) ? nkk : 0) + r0;   // Bh, Bl, Bh
        uint32_t st = (uint32_t)(c & 1) * STAGEB;
#pragma unroll
        for (int i = 0; i < 2; ++i) cp16(adst[i] + st, asrc[i] + ka * 32);
#pragma unroll
        for (int i = 0; i < 2; ++i) cp16(bdst[i] + st, bsrc[i] + kb * 32);
        cp_commit();
    };

    // ---- ldmatrix per-thread addresses (stage/k-step invariant) ------------
    uint32_t aAddr[2];
#pragma unroll
    for (int m = 0; m < 2; ++m) {
        int row = warp_m * 32 + m * 16 + (lane & 15);
        aAddr[m] = sb + (uint32_t)(row * ROWB + (lane >> 4) * 16);
    }
    uint32_t bAddr[4];
#pragma unroll
    for (int p = 0; p < 4; ++p) {
        int row = warp_n * 64 + (2 * p + (lane >> 4)) * 8 + (lane & 7);
        bAddr[p] = sb + TILEB + (uint32_t)(row * ROWB + ((lane >> 3) & 1) * 16);
    }

    float acc[2][8][4];
#pragma unroll
    for (int m = 0; m < 2; ++m)
#pragma unroll
        for (int n = 0; n < 8; ++n)
#pragma unroll
            for (int j = 0; j < 4; ++j) acc[m][n][j] = 0.0f;

    issue(0);

    for (int s = 0; s < nc; ++s) {
        if (s + 1 < nc) {
            issue(s + 1);
            asm volatile("cp.async.wait_group 1;" ::: "memory");
        } else {
            asm volatile("cp.async.wait_group 0;" ::: "memory");
        }
        __syncthreads();

        const uint32_t st = (uint32_t)(s & 1) * STAGEB;
#pragma unroll
        for (int ks = 0; ks < 2; ++ks) {
            uint32_t a[2][4], b[4][4];
#pragma unroll
            for (int m = 0; m < 2; ++m)
                LDSM4(a[m][0], a[m][1], a[m][2], a[m][3], aAddr[m] + st + ks * 32);
#pragma unroll
            for (int p = 0; p < 4; ++p)
                LDSM4(b[p][0], b[p][1], b[p][2], b[p][3], bAddr[p] + st + ks * 32);
#pragma unroll
            for (int m = 0; m < 2; ++m)
#pragma unroll
                for (int n = 0; n < 8; ++n)
                    MMA16816(acc[m][n], a[m], b[n >> 1][(n & 1) * 2], b[n >> 1][(n & 1) * 2 + 1]);
        }
        __syncthreads();
    }

    // ---- epilogue: write fp32 C (+ optional bias) ---------------------------
#pragma unroll
    for (int m = 0; m < 2; ++m) {
        const int r0 = bm + warp_m * 32 + m * 16 + (lane >> 2);
#pragma unroll
        for (int n = 0; n < 8; ++n) {
            const int c0 = bn + warp_n * 64 + n * 8 + (lane & 3) * 2;
            float2 v0 = make_float2(acc[m][n][0], acc[m][n][1]);
            float2 v1 = make_float2(acc[m][n][2], acc[m][n][3]);
            if (BIAS) {
                float bx = __ldg(&bias[c0]), by = __ldg(&bias[c0 + 1]);
                v0.x += bx; v0.y += by; v1.x += bx; v1.y += by;
            }
            *(float2*)(C + (size_t)r0 * Nn + c0)       = v0;
            *(float2*)(C + (size_t)(r0 + 8) * Nn + c0) = v1;
        }
    }
}

// ---------------------------------------------------------------------------
// fp32 -> bf16 hi/lo split:  dst[row, j] = hi, dst[row, K + j] = lo
// ---------------------------------------------------------------------------
__global__ void conv_split(const float* __restrict__ src, __nv_bfloat16* __restrict__ dst,
                           int rows, int K)
{
    const int idx = blockIdx.x * blockDim.x + threadIdx.x;
    const int per = K >> 2;
    const int row = idx / per;
    const int j   = (idx - row * per) << 2;
    if (row >= rows) return;
    float4 v = *(const float4*)(src + (size_t)row * K + j);
    __nv_bfloat16 h0 = __float2bfloat16_rn(v.x), h1 = __float2bfloat16_rn(v.y);
    __nv_bfloat16 h2 = __float2bfloat16_rn(v.z), h3 = __float2bfloat16_rn(v.w);
    __nv_bfloat16 l0 = __float2bfloat16_rn(v.x - __bfloat162float(h0));
    __nv_bfloat16 l1 = __float2bfloat16_rn(v.y - __bfloat162float(h1));
    __nv_bfloat16 l2 = __float2bfloat16_rn(v.z - __bfloat162float(h2));
    __nv_bfloat16 l3 = __float2bfloat16_rn(v.w - __bfloat162float(h3));
    uint2 hh, ll;
    hh.x = ((uint32_t)__bfloat16_as_ushort(h1) << 16) | __bfloat16_as_ushort(h0);
    hh.y = ((uint32_t)__bfloat16_as_ushort(h3) << 16) | __bfloat16_as_ushort(h2);
    ll.x = ((uint32_t)__bfloat16_as_ushort(l1) << 16) | __bfloat16_as_ushort(l0);
    ll.y = ((uint32_t)__bfloat16_as_ushort(l3) << 16) | __bfloat16_as_ushort(l2);
    *(uint2*)(dst + (size_t)row * 2 * K + j)     = hh;
    *(uint2*)(dst + (size_t)row * 2 * K + K + j) = ll;
}

// ---------------------------------------------------------------------------
// Layer epilogue: window-sum + bias + PReLU, output bf16 hi/lo [N, 512]
// ---------------------------------------------------------------------------
__global__ void layer_epi(const float* __restrict__ Y, const float* __restrict__ bias,
                          const float* __restrict__ ea, const float* __restrict__ aslope,
                          __nv_bfloat16* __restrict__ Aout)
{
    const int idx = blockIdx.x * blockDim.x + threadIdx.x;
    const int row = idx >> 6;
    const int c4  = idx & 63;
    const int t   = row & (LSEQ - 1);

    const int starts[8] = {0, 2047, 4093, 6138, 8182, 10225, 12267, 14308};
    float w[8];
#pragma unroll
    for (int d = 0; d < 8; ++d) w[d] = __ldg(&ea[starts[d]]);

    const float4* Yv = (const float4*)Y;
    float4 v = Yv[(size_t)row * 128 + 64 + c4];       // root half
    float4 b = *(const float4*)&bias[c4 * 4];
    v.x += b.x; v.y += b.y; v.z += b.z; v.w += b.w;

#pragma unroll
    for (int d = 1; d <= 8; ++d) {
        if (t >= d) {
            float4 r = Yv[(size_t)(row - d) * 128 + c4];   // rel half, shifted
            const float wd = w[d - 1];
            v.x = fmaf(wd, r.x, v.x); v.y = fmaf(wd, r.y, v.y);
            v.z = fmaf(wd, r.z, v.z); v.w = fmaf(wd, r.w, v.w);
        }
    }
    const float a = __ldg(aslope);
    v.x = v.x >= 0.f ? v.x : a * v.x;
    v.y = v.y >= 0.f ? v.y : a * v.y;
    v.z = v.z >= 0.f ? v.z : a * v.z;
    v.w = v.w >= 0.f ? v.w : a * v.w;

    __nv_bfloat16 h0 = __float2bfloat16_rn(v.x), h1 = __float2bfloat16_rn(v.y);
    __nv_bfloat16 h2 = __float2bfloat16_rn(v.z), h3 = __float2bfloat16_rn(v.w);
    __nv_bfloat16 l0 = __float2bfloat16_rn(v.x - __bfloat162float(h0));
    __nv_bfloat16 l1 = __float2bfloat16_rn(v.y - __bfloat162float(h1));
    __nv_bfloat16 l2 = __float2bfloat16_rn(v.z - __bfloat162float(h2));
    __nv_bfloat16 l3 = __float2bfloat16_rn(v.w - __bfloat162float(h3));
    uint2 hh, ll;
    hh.x = ((uint32_t)__bfloat16_as_ushort(h1) << 16) | __bfloat16_as_ushort(h0);
    hh.y = ((uint32_t)__bfloat16_as_ushort(h3) << 16) | __bfloat16_as_ushort(h2);
    ll.x = ((uint32_t)__bfloat16_as_ushort(l1) << 16) | __bfloat16_as_ushort(l0);
    ll.y = ((uint32_t)__bfloat16_as_ushort(l3) << 16) | __bfloat16_as_ushort(l2);
    *(uint2*)(Aout + (size_t)row * 512 + c4 * 4)       = hh;
    *(uint2*)(Aout + (size_t)row * 512 + 256 + c4 * 4) = ll;
}

// ---------------------------------------------------------------------------
extern "C" void kernel_launch(void* const* d_in, const int* in_sizes, int n_in,
                              void* d_out, int out_size)
{
    const float* X       = (const float*)d_in[0];
    const float* W_rel1  = (const float*)d_in[1];
    const float* b_rel1  = (const float*)d_in[2];
    const float* W_root1 = (const float*)d_in[3];
    const float* W_rel2  = (const float*)d_in[4];
    const float* b_rel2  = (const float*)d_in[5];
    const float* W_root2 = (const float*)d_in[6];
    const float* a1      = (const float*)d_in[7];
    const float* a2      = (const float*)d_in[8];
    const float* W_fc    = (const float*)d_in[9];
    const float* b_fc    = (const float*)d_in[10];
    const float* ea      = (const float*)d_in[11];
    float*       out     = (float*)d_out;

    __nv_bfloat16 *A1, *A2, *B1, *B2, *Bf;
    float* Y;
    cudaGetSymbolAddress((void**)&A1, g_A1);
    cudaGetSymbolAddress((void**)&A2, g_A2);
    cudaGetSymbolAddress((void**)&Y,  g_Y);
    cudaGetSymbolAddress((void**)&B1, g_B1);
    cudaGetSymbolAddress((void**)&B2, g_B2);
    cudaGetSymbolAddress((void**)&Bf, g_Bf);

    // hi/lo splits
    conv_split<<<(NNODE * 32) / 256, 256>>>(X, A1, NNODE, 128);
    conv_split<<<32, 256>>>(W_rel1,  B1,             256, 128);
    conv_split<<<32, 256>>>(W_root1, B1 + 256 * 256, 256, 128);
    conv_split<<<64, 256>>>(W_rel2,  B2,             256, 256);
    conv_split<<<64, 256>>>(W_root2, B2 + 256 * 512, 256, 256);
    conv_split<<<32, 256>>>(W_fc,    Bf,             128, 256);

    // Layer 1: Y = X' @ [W1h|W1l]^T (split-3)
    gemm_mma<false><<<dim3(4, 256), 256>>>(A1, B1, Y, nullptr, 128, 512);
    layer_epi<<<NNODE * 64 / 256, 256>>>(Y, b_rel1, ea, a1, A2);
    // Layer 2
    gemm_mma<false><<<dim3(4, 256), 256>>>(A2, B2, Y, nullptr, 256, 512);
    layer_epi<<<NNODE * 64 / 256, 256>>>(Y, b_rel2, ea, a2, A2);
    // FC
    gemm_mma<true><<<dim3(1, 256), 256>>>(A2, Bf, out, b_fc, 256, 128);
}

// round 4
// speedup vs baseline: 2.2520x; 1.2157x over previous
#include <cuda_runtime.h>
#include <cuda_bf16.h>
#include <cstdint>

#define NNODE 32768
#define LSEQ  2048

// ---------------- device scratch (no allocation allowed) -------------------
__device__ __align__(16) __nv_bfloat16 g_A1 [NNODE * 256];   // [N, 2*128]  X hi|lo
__device__ __align__(16) __nv_bfloat16 g_A2 [NNODE * 512];   // [N, 2*256]  H1 hi|lo
__device__ __align__(16) __nv_bfloat16 g_A3 [NNODE * 512];   // [N, 2*256]  H2 hi|lo
__device__ __align__(16) __nv_bfloat16 g_SA [NNODE * 128];   // [N, 128]  S.X
__device__ __align__(16) __nv_bfloat16 g_SH [NNODE * 256];   // [N, 256]  S.H1
__device__ __align__(16) __nv_bfloat16 g_B1s[256 * 512];     // [Wrel1h|Wroot1h|Wroot1l|Wroot1h]
__device__ __align__(16) __nv_bfloat16 g_B2s[256 * 1024];    // same, K=256
__device__ __align__(16) __nv_bfloat16 g_Bfs[128 * 768];     // [Wfch|Wfcl|Wfch]

// ---------------- PTX helpers ----------------------------------------------
static __device__ __forceinline__ void cp16(uint32_t dst, const void* src) {
    asm volatile("cp.async.cg.shared.global [%0], [%1], 16;" :: "r"(dst), "l"(src) : "memory");
}
static __device__ __forceinline__ void cp_commit() {
    asm volatile("cp.async.commit_group;" ::: "memory");
}

#define LDSM4(r0, r1, r2, r3, a) \
    asm volatile("ldmatrix.sync.aligned.m8n8.x4.shared.b16 {%0,%1,%2,%3}, [%4];" \
                 : "=r"(r0), "=r"(r1), "=r"(r2), "=r"(r3) : "r"(a))

#define MMA16816(d, a, b0, b1) \
    asm volatile("mma.sync.aligned.m16n8k16.row.col.f32.bf16.bf16.f32 " \
                 "{%0,%1,%2,%3}, {%4,%5,%6,%7}, {%8,%9}, {%0,%1,%2,%3};" \
                 : "+f"((d)[0]), "+f"((d)[1]), "+f"((d)[2]), "+f"((d)[3]) \
                 : "r"((a)[0]), "r"((a)[1]), "r"((a)[2]), "r"((a)[3]), \
                   "r"(b0), "r"(b1))

static __device__ __forceinline__ uint32_t pack_bf16(float x, float y) {
    __nv_bfloat16 h0 = __float2bfloat16_rn(x), h1 = __float2bfloat16_rn(y);
    return ((uint32_t)__bfloat16_as_ushort(h1) << 16) | __bfloat16_as_ushort(h0);
}

// ---------------------------------------------------------------------------
// Segmented-K bf16 HMMA GEMM (mma.sync m16n8k16), virtual K = NSEG*KK.
// A segment s: rows from Ab[s] with leading dim Al[s] (K-major bf16).
// B: pre-stacked [Nout, NSEG*KK] bf16 (K-major).
// LAYER=true : epilogue = +bias, PReLU(slope), hi/lo bf16 split -> Aout
// LAYER=false: epilogue = +bias, fp32 store (ldout = ldc)
// CTA tile 128x128, BK=32, 8 warps (4M x 2N), 2-stage cp.async.
// ---------------------------------------------------------------------------
#define ROWB   80
#define TILEB  (128 * ROWB)
#define STAGEB (2 * TILEB)

template <int NSEG, bool LAYER>
__global__ __launch_bounds__(256)
void gemm_mma(const __nv_bfloat16* __restrict__ A0, const __nv_bfloat16* __restrict__ A1p,
              const __nv_bfloat16* __restrict__ A2p, const __nv_bfloat16* __restrict__ A3p,
              int l0, int l1, int l2, int l3,
              const __nv_bfloat16* __restrict__ Bs,
              const float* __restrict__ bias, const float* __restrict__ slope,
              void* __restrict__ OutP, int KK, int ldout)
{
    __shared__ __align__(16) char smem[2 * STAGEB];   // 40960 B
    const uint32_t sb = (uint32_t)__cvta_generic_to_shared(smem);

    const int tid    = threadIdx.x;
    const int lane   = tid & 31;
    const int wid    = tid >> 5;
    const int warp_m = wid & 3;
    const int warp_n = wid >> 2;
    const int bm     = blockIdx.y * 128;
    const int bn     = blockIdx.x * 128;
    const int ldb    = NSEG * KK;
    const int nkk    = KK >> 5;
    const int nc     = NSEG * nkk;

    // per-thread load geometry (2 16B units for A, 2 for B)
    int rA[2], qA[2];
    const __nv_bfloat16* bsrc[2]; uint32_t adst[2], bdst[2];
#pragma unroll
    for (int i = 0; i < 2; ++i) {
        int u = i * 256 + tid, r = u >> 2, q = u & 3;
        rA[i] = r; qA[i] = q;
        adst[i] = sb + (uint32_t)(r * ROWB + q * 16);
        bsrc[i] = Bs + (size_t)(bn + r) * ldb + q * 8;
        bdst[i] = sb + TILEB + (uint32_t)(r * ROWB + q * 16);
    }

    auto issue = [&](int c) {
        int seg;
        if (NSEG == 4) seg = (c >= 3 * nkk) ? 3 : (c >= 2 * nkk) ? 2 : (c >= nkk) ? 1 : 0;
        else           seg = (c >= 2 * nkk) ? 2 : (c >= nkk) ? 1 : 0;
        const __nv_bfloat16* ab; int al;
        if      (seg == 0) { ab = A0;  al = l0; }
        else if (seg == 1) { ab = A1p; al = l1; }
        else if (seg == 2) { ab = A2p; al = l2; }
        else               { ab = A3p; al = l3; }
        const __nv_bfloat16* arow = ab + (size_t)bm * al + (c - seg * nkk) * 32;
        uint32_t st = (uint32_t)(c & 1) * STAGEB;
#pragma unroll
        for (int i = 0; i < 2; ++i) cp16(adst[i] + st, arow + (size_t)rA[i] * al + qA[i] * 8);
#pragma unroll
        for (int i = 0; i < 2; ++i) cp16(bdst[i] + st, bsrc[i] + c * 32);
        cp_commit();
    };

    // ldmatrix addresses (stage/k-step invariant)
    uint32_t aAddr[2];
#pragma unroll
    for (int m = 0; m < 2; ++m) {
        int row = warp_m * 32 + m * 16 + (lane & 15);
        aAddr[m] = sb + (uint32_t)(row * ROWB + (lane >> 4) * 16);
    }
    uint32_t bAddr[4];
#pragma unroll
    for (int p = 0; p < 4; ++p) {
        int row = warp_n * 64 + (2 * p + (lane >> 4)) * 8 + (lane & 7);
        bAddr[p] = sb + TILEB + (uint32_t)(row * ROWB + ((lane >> 3) & 1) * 16);
    }

    float acc[2][8][4];
#pragma unroll
    for (int m = 0; m < 2; ++m)
#pragma unroll
        for (int n = 0; n < 8; ++n)
#pragma unroll
            for (int j = 0; j < 4; ++j) acc[m][n][j] = 0.0f;

    issue(0);

    for (int s = 0; s < nc; ++s) {
        if (s + 1 < nc) {
            issue(s + 1);
            asm volatile("cp.async.wait_group 1;" ::: "memory");
        } else {
            asm volatile("cp.async.wait_group 0;" ::: "memory");
        }
        __syncthreads();

        const uint32_t st = (uint32_t)(s & 1) * STAGEB;
#pragma unroll
        for (int ks = 0; ks < 2; ++ks) {
            uint32_t a[2][4], b[4][4];
#pragma unroll
            for (int m = 0; m < 2; ++m)
                LDSM4(a[m][0], a[m][1], a[m][2], a[m][3], aAddr[m] + st + ks * 32);
#pragma unroll
            for (int p = 0; p < 4; ++p)
                LDSM4(b[p][0], b[p][1], b[p][2], b[p][3], bAddr[p] + st + ks * 32);
#pragma unroll
            for (int m = 0; m < 2; ++m)
#pragma unroll
                for (int n = 0; n < 8; ++n)
                    MMA16816(acc[m][n], a[m], b[n >> 1][(n & 1) * 2], b[n >> 1][(n & 1) * 2 + 1]);
        }
        __syncthreads();
    }

    // ---- epilogue ----------------------------------------------------------
    if (LAYER) {
        __nv_bfloat16* Aout = (__nv_bfloat16*)OutP;
        const int KKout = ldout >> 1;
        const float a = __ldg(slope);
#pragma unroll
        for (int m = 0; m < 2; ++m) {
            const int r0 = bm + warp_m * 32 + m * 16 + (lane >> 2);
#pragma unroll
            for (int n = 0; n < 8; ++n) {
                const int c0 = bn + warp_n * 64 + n * 8 + (lane & 3) * 2;
                const float bx = __ldg(&bias[c0]), by = __ldg(&bias[c0 + 1]);
#pragma unroll
                for (int h = 0; h < 2; ++h) {
                    float vx = acc[m][n][h * 2 + 0] + bx;
                    float vy = acc[m][n][h * 2 + 1] + by;
                    vx = vx >= 0.f ? vx : a * vx;
                    vy = vy >= 0.f ? vy : a * vy;
                    __nv_bfloat16 hx = __float2bfloat16_rn(vx), hy = __float2bfloat16_rn(vy);
                    float rx = vx - __bfloat162float(hx), ry = vy - __bfloat162float(hy);
                    uint32_t hi = ((uint32_t)__bfloat16_as_ushort(hy) << 16) | __bfloat16_as_ushort(hx);
                    uint32_t lo = pack_bf16(rx, ry);
                    const size_t base = (size_t)(r0 + h * 8) * ldout + c0;
                    *(uint32_t*)&Aout[base]         = hi;
                    *(uint32_t*)&Aout[base + KKout] = lo;
                }
            }
        }
    } else {
        float* C = (float*)OutP;
#pragma unroll
        for (int m = 0; m < 2; ++m) {
            const int r0 = bm + warp_m * 32 + m * 16 + (lane >> 2);
#pragma unroll
            for (int n = 0; n < 8; ++n) {
                const int c0 = bn + warp_n * 64 + n * 8 + (lane & 3) * 2;
                const float bx = __ldg(&bias[c0]), by = __ldg(&bias[c0 + 1]);
                *(float2*)(C + (size_t)r0 * ldout + c0) =
                    make_float2(acc[m][n][0] + bx, acc[m][n][1] + by);
                *(float2*)(C + (size_t)(r0 + 8) * ldout + c0) =
                    make_float2(acc[m][n][2] + bx, acc[m][n][3] + by);
            }
        }
    }
}

// ---------------------------------------------------------------------------
// Weight prep: hi -> dst+offH, lo -> dst+offL (if >=0), hi dup -> dst+offH2
// ---------------------------------------------------------------------------
__global__ void split_w(const float* __restrict__ src, __nv_bfloat16* __restrict__ dst,
                        int ldb, int offH, int offL, int offH2, int rows, int K)
{
    const int idx = blockIdx.x * blockDim.x + threadIdx.x;
    const int per = K >> 2;
    const int row = idx / per;
    const int j   = (idx - row * per) << 2;
    if (row >= rows) return;
    float4 v = *(const float4*)(src + (size_t)row * K + j);
    __nv_bfloat16 h0 = __float2bfloat16_rn(v.x), h1 = __float2bfloat16_rn(v.y);
    __nv_bfloat16 h2 = __float2bfloat16_rn(v.z), h3 = __float2bfloat16_rn(v.w);
    uint2 hh;
    hh.x = ((uint32_t)__bfloat16_as_ushort(h1) << 16) | __bfloat16_as_ushort(h0);
    hh.y = ((uint32_t)__bfloat16_as_ushort(h3) << 16) | __bfloat16_as_ushort(h2);
    *(uint2*)(dst + (size_t)row * ldb + offH + j) = hh;
    if (offL >= 0) {
        uint2 ll;
        ll.x = pack_bf16(v.x - __bfloat162float(h0), v.y - __bfloat162float(h1));
        ll.y = pack_bf16(v.z - __bfloat162float(h2), v.w - __bfloat162float(h3));
        *(uint2*)(dst + (size_t)row * ldb + offL + j) = ll;
    }
    if (offH2 >= 0)
        *(uint2*)(dst + (size_t)row * ldb + offH2 + j) = hh;
}

// ---------------------------------------------------------------------------
// prep_x: X fp32 [N,128] -> A1 hi|lo [N,256] bf16, SA = S.X [N,128] bf16
// ---------------------------------------------------------------------------
__global__ void prep_x(const float* __restrict__ X, const float* __restrict__ ea,
                       __nv_bfloat16* __restrict__ A1, __nv_bfloat16* __restrict__ SA)
{
    const int idx = blockIdx.x * blockDim.x + threadIdx.x;
    const int row = idx >> 5;
    const int col = (idx & 31) << 2;
    const int t   = row & (LSEQ - 1);

    float4 v = *(const float4*)(X + (size_t)row * 128 + col);
    __nv_bfloat16 h0 = __float2bfloat16_rn(v.x), h1 = __float2bfloat16_rn(v.y);
    __nv_bfloat16 h2 = __float2bfloat16_rn(v.z), h3 = __float2bfloat16_rn(v.w);
    uint2 hh, ll;
    hh.x = ((uint32_t)__bfloat16_as_ushort(h1) << 16) | __bfloat16_as_ushort(h0);
    hh.y = ((uint32_t)__bfloat16_as_ushort(h3) << 16) | __bfloat16_as_ushort(h2);
    ll.x = pack_bf16(v.x - __bfloat162float(h0), v.y - __bfloat162float(h1));
    ll.y = pack_bf16(v.z - __bfloat162float(h2), v.w - __bfloat162float(h3));
    *(uint2*)(A1 + (size_t)row * 256 + col)       = hh;
    *(uint2*)(A1 + (size_t)row * 256 + 128 + col) = ll;

    const int starts[8] = {0, 2047, 4093, 6138, 8182, 10225, 12267, 14308};
    float4 s = make_float4(0.f, 0.f, 0.f, 0.f);
#pragma unroll
    for (int d = 1; d <= 8; ++d) {
        if (t >= d) {
            const float wd = __ldg(&ea[starts[d - 1]]);
            float4 xd = *(const float4*)(X + (size_t)(row - d) * 128 + col);
            s.x = fmaf(wd, xd.x, s.x); s.y = fmaf(wd, xd.y, s.y);
            s.z = fmaf(wd, xd.z, s.z); s.w = fmaf(wd, xd.w, s.w);
        }
    }
    uint2 so;
    so.x = pack_bf16(s.x, s.y);
    so.y = pack_bf16(s.z, s.w);
    *(uint2*)(SA + (size_t)row * 128 + col) = so;
}

// ---------------------------------------------------------------------------
// shift_h: SH[i,:] = sum_d w_d * Hh[i-d,:]   (Hh = hi half of [N, 512] layout)
// ---------------------------------------------------------------------------
__global__ void shift_h(const __nv_bfloat16* __restrict__ Hh, const float* __restrict__ ea,
                        __nv_bfloat16* __restrict__ SH)
{
    const int idx = blockIdx.x * blockDim.x + threadIdx.x;
    const int row = idx >> 6;
    const int col = (idx & 63) << 2;
    const int t   = row & (LSEQ - 1);

    const int starts[8] = {0, 2047, 4093, 6138, 8182, 10225, 12267, 14308};
    float4 s = make_float4(0.f, 0.f, 0.f, 0.f);
#pragma unroll
    for (int d = 1; d <= 8; ++d) {
        if (t >= d) {
            const float wd = __ldg(&ea[starts[d - 1]]);
            uint2 u = *(const uint2*)(Hh + (size_t)(row - d) * 512 + col);
            s.x = fmaf(wd, __bfloat162float(__ushort_as_bfloat16((ushort)(u.x & 0xFFFF))), s.x);
            s.y = fmaf(wd, __bfloat162float(__ushort_as_bfloat16((ushort)(u.x >> 16))),    s.y);
            s.z = fmaf(wd, __bfloat162float(__ushort_as_bfloat16((ushort)(u.y & 0xFFFF))), s.z);
            s.w = fmaf(wd, __bfloat162float(__ushort_as_bfloat16((ushort)(u.y >> 16))),    s.w);
        }
    }
    uint2 so;
    so.x = pack_bf16(s.x, s.y);
    so.y = pack_bf16(s.z, s.w);
    *(uint2*)(SH + (size_t)row * 256 + col) = so;
}

// ---------------------------------------------------------------------------
extern "C" void kernel_launch(void* const* d_in, const int* in_sizes, int n_in,
                              void* d_out, int out_size)
{
    const float* X       = (const float*)d_in[0];
    const float* W_rel1  = (const float*)d_in[1];
    const float* b_rel1  = (const float*)d_in[2];
    const float* W_root1 = (const float*)d_in[3];
    const float* W_rel2  = (const float*)d_in[4];
    const float* b_rel2  = (const float*)d_in[5];
    const float* W_root2 = (const float*)d_in[6];
    const float* a1      = (const float*)d_in[7];
    const float* a2      = (const float*)d_in[8];
    const float* W_fc    = (const float*)d_in[9];
    const float* b_fc    = (const float*)d_in[10];
    const float* ea      = (const float*)d_in[11];
    float*       out     = (float*)d_out;

    __nv_bfloat16 *A1, *A2, *A3, *SA, *SH, *B1s, *B2s, *Bfs;
    cudaGetSymbolAddress((void**)&A1,  g_A1);
    cudaGetSymbolAddress((void**)&A2,  g_A2);
    cudaGetSymbolAddress((void**)&A3,  g_A3);
    cudaGetSymbolAddress((void**)&SA,  g_SA);
    cudaGetSymbolAddress((void**)&SH,  g_SH);
    cudaGetSymbolAddress((void**)&B1s, g_B1s);
    cudaGetSymbolAddress((void**)&B2s, g_B2s);
    cudaGetSymbolAddress((void**)&Bfs, g_Bfs);

    // weight stacks
    split_w<<<32, 256>>>(W_rel1,  B1s,  512,   0,  -1,  -1, 256, 128);
    split_w<<<32, 256>>>(W_root1, B1s,  512, 128, 256, 384, 256, 128);
    split_w<<<64, 256>>>(W_rel2,  B2s, 1024,   0,  -1,  -1, 256, 256);
    split_w<<<64, 256>>>(W_root2, B2s, 1024, 256, 512, 768, 256, 256);
    split_w<<<32, 256>>>(W_fc,    Bfs,  768,   0, 256, 512, 128, 256);

    // X: hi/lo split + window shift
    prep_x<<<NNODE * 32 / 256, 256>>>(X, ea, A1, SA);

    // Layer 1: H1 = prelu([S.X | Xh | Xh | Xl] @ [Wrel1h|Wroot1h|Wroot1l|Wroot1h]^T + b1)
    gemm_mma<4, true><<<dim3(2, 256), 256>>>(SA, A1, A1, A1 + 128,
                                             128, 256, 256, 256,
                                             B1s, b_rel1, a1, A2, 128, 512);
    // S.H1
    shift_h<<<NNODE * 64 / 256, 256>>>(A2, ea, SH);

    // Layer 2
    gemm_mma<4, true><<<dim3(2, 256), 256>>>(SH, A2, A2, A2 + 256,
                                             256, 512, 512, 512,
                                             B2s, b_rel2, a2, A3, 256, 512);
    // FC: out = [H2h|H2h|H2l] @ [Wfch|Wfcl|Wfch]^T + b_fc
    gemm_mma<3, false><<<dim3(1, 256), 256>>>(A3, A3, A3 + 256, A3,
                                              512, 512, 512, 512,
                                              Bfs, b_fc, nullptr, out, 256, 128);
}

// round 5
// speedup vs baseline: 2.5537x; 1.1340x over previous
#include <cuda_runtime.h>
#include <cuda_bf16.h>
#include <cstdint>

#define NNODE 32768
#define LSEQ  2048

// ---------------- device scratch (no allocation allowed) -------------------
__device__ __align__(16) __nv_bfloat16 g_A1 [NNODE * 256];   // [N, 2*128]  X hi|lo
__device__ __align__(16) __nv_bfloat16 g_A2 [NNODE * 512];   // [N, 2*256]  H1 hi|lo
__device__ __align__(16) __nv_bfloat16 g_A3 [NNODE * 512];   // [N, 2*256]  H2 hi|lo
__device__ __align__(16) __nv_bfloat16 g_SA [NNODE * 128];   // [N, 128]  S.X
__device__ __align__(16) __nv_bfloat16 g_SH [NNODE * 256];   // [N, 256]  S.H1
__device__ __align__(16) __nv_bfloat16 g_B1s[256 * 512];     // [Wrel1h|Wroot1h|Wroot1l|Wroot1h]
__device__ __align__(16) __nv_bfloat16 g_B2s[256 * 1024];    // same, K=256
__device__ __align__(16) __nv_bfloat16 g_Bfs[128 * 768];     // [Wfch|Wfcl|Wfch]

// ---------------- PTX helpers ----------------------------------------------
static __device__ __forceinline__ void cp16(uint32_t dst, const void* src) {
    asm volatile("cp.async.cg.shared.global [%0], [%1], 16;" :: "r"(dst), "l"(src) : "memory");
}
static __device__ __forceinline__ void cp_commit() {
    asm volatile("cp.async.commit_group;" ::: "memory");
}

#define LDSM4(r0, r1, r2, r3, a) \
    asm volatile("ldmatrix.sync.aligned.m8n8.x4.shared.b16 {%0,%1,%2,%3}, [%4];" \
                 : "=r"(r0), "=r"(r1), "=r"(r2), "=r"(r3) : "r"(a))

#define MMA16816(d, a, b0, b1) \
    asm volatile("mma.sync.aligned.m16n8k16.row.col.f32.bf16.bf16.f32 " \
                 "{%0,%1,%2,%3}, {%4,%5,%6,%7}, {%8,%9}, {%0,%1,%2,%3};" \
                 : "+f"((d)[0]), "+f"((d)[1]), "+f"((d)[2]), "+f"((d)[3]) \
                 : "r"((a)[0]), "r"((a)[1]), "r"((a)[2]), "r"((a)[3]), \
                   "r"(b0), "r"(b1))

static __device__ __forceinline__ uint32_t pack_bf16(float x, float y) {
    __nv_bfloat16 h0 = __float2bfloat16_rn(x), h1 = __float2bfloat16_rn(y);
    return ((uint32_t)__bfloat16_as_ushort(h1) << 16) | __bfloat16_as_ushort(h0);
}

// ---------------------------------------------------------------------------
// Segmented-K bf16 HMMA GEMM, virtual K = NSEG*KK, 4-stage cp.async pipeline.
// CTA tile 128x128, BK=32, 8 warps (4M x 2N), one __syncthreads per chunk.
// ---------------------------------------------------------------------------
#define ROWB   80
#define TILEB  (128 * ROWB)          // 10240
#define STAGEB (2 * TILEB)           // 20480
#define NSTG   4

template <int NSEG, bool LAYER>
__global__ __launch_bounds__(256, 2)
void gemm_mma(const __nv_bfloat16* __restrict__ A0, const __nv_bfloat16* __restrict__ A1p,
              const __nv_bfloat16* __restrict__ A2p, const __nv_bfloat16* __restrict__ A3p,
              int l0, int l1, int l2, int l3,
              const __nv_bfloat16* __restrict__ Bs,
              const float* __restrict__ bias, const float* __restrict__ slope,
              void* __restrict__ OutP, int KK, int ldout)
{
    extern __shared__ __align__(16) char smem[];   // NSTG * STAGEB = 81920
    const uint32_t sb = (uint32_t)__cvta_generic_to_shared(smem);

    const int tid    = threadIdx.x;
    const int lane   = tid & 31;
    const int wid    = tid >> 5;
    const int warp_m = wid & 3;
    const int warp_n = wid >> 2;
    const int bm     = blockIdx.y * 128;
    const int bn     = blockIdx.x * 128;
    const int ldb    = NSEG * KK;
    const int nkk    = KK >> 5;
    const int nc     = NSEG * nkk;

    // per-thread load geometry (2 16B units for A, 2 for B)
    int rA[2], qA[2];
    const __nv_bfloat16* bsrc[2]; uint32_t adst[2], bdst[2];
#pragma unroll
    for (int i = 0; i < 2; ++i) {
        int u = i * 256 + tid, r = u >> 2, q = u & 3;
        rA[i] = r; qA[i] = q;
        adst[i] = sb + (uint32_t)(r * ROWB + q * 16);
        bsrc[i] = Bs + (size_t)(bn + r) * ldb + q * 8;
        bdst[i] = sb + TILEB + (uint32_t)(r * ROWB + q * 16);
    }

    auto issue = [&](int c) {
        if (c < nc) {
            int seg;
            if (NSEG == 4) seg = (c >= 3 * nkk) ? 3 : (c >= 2 * nkk) ? 2 : (c >= nkk) ? 1 : 0;
            else           seg = (c >= 2 * nkk) ? 2 : (c >= nkk) ? 1 : 0;
            const __nv_bfloat16* ab; int al;
            if      (seg == 0) { ab = A0;  al = l0; }
            else if (seg == 1) { ab = A1p; al = l1; }
            else if (seg == 2) { ab = A2p; al = l2; }
            else               { ab = A3p; al = l3; }
            const __nv_bfloat16* arow = ab + (size_t)bm * al + (c - seg * nkk) * 32;
            uint32_t st = (uint32_t)(c & (NSTG - 1)) * STAGEB;
#pragma unroll
            for (int i = 0; i < 2; ++i) cp16(adst[i] + st, arow + (size_t)rA[i] * al + qA[i] * 8);
#pragma unroll
            for (int i = 0; i < 2; ++i) cp16(bdst[i] + st, bsrc[i] + c * 32);
        }
        cp_commit();   // always commit (dummy groups keep wait_group counting valid)
    };

    // ldmatrix addresses (stage/k-step invariant)
    uint32_t aAddr[2];
#pragma unroll
    for (int m = 0; m < 2; ++m) {
        int row = warp_m * 32 + m * 16 + (lane & 15);
        aAddr[m] = sb + (uint32_t)(row * ROWB + (lane >> 4) * 16);
    }
    uint32_t bAddr[4];
#pragma unroll
    for (int p = 0; p < 4; ++p) {
        int row = warp_n * 64 + (2 * p + (lane >> 4)) * 8 + (lane & 7);
        bAddr[p] = sb + TILEB + (uint32_t)(row * ROWB + ((lane >> 3) & 1) * 16);
    }

    float acc[2][8][4];
#pragma unroll
    for (int m = 0; m < 2; ++m)
#pragma unroll
        for (int n = 0; n < 8; ++n)
#pragma unroll
            for (int j = 0; j < 4; ++j) acc[m][n][j] = 0.0f;

    // prologue: stages 0..2
    issue(0); issue(1); issue(2);

    for (int s = 0; s < nc; ++s) {
        asm volatile("cp.async.wait_group 2;" ::: "memory");  // chunk s resident
        __syncthreads();                                       // + all warps done with s-1's buffer
        issue(s + 3);                                          // refill (s-1)'s buffer

        const uint32_t st = (uint32_t)(s & (NSTG - 1)) * STAGEB;
#pragma unroll
        for (int ks = 0; ks < 2; ++ks) {
            uint32_t a[2][4], b[4][4];
#pragma unroll
            for (int m = 0; m < 2; ++m)
                LDSM4(a[m][0], a[m][1], a[m][2], a[m][3], aAddr[m] + st + ks * 32);
#pragma unroll
            for (int p = 0; p < 4; ++p)
                LDSM4(b[p][0], b[p][1], b[p][2], b[p][3], bAddr[p] + st + ks * 32);
#pragma unroll
            for (int m = 0; m < 2; ++m)
#pragma unroll
                for (int n = 0; n < 8; ++n)
                    MMA16816(acc[m][n], a[m], b[n >> 1][(n & 1) * 2], b[n >> 1][(n & 1) * 2 + 1]);
        }
    }

    // ---- epilogue ----------------------------------------------------------
    if (LAYER) {
        __nv_bfloat16* Aout = (__nv_bfloat16*)OutP;
        const int KKout = ldout >> 1;
        const float a = __ldg(slope);
#pragma unroll
        for (int m = 0; m < 2; ++m) {
            const int r0 = bm + warp_m * 32 + m * 16 + (lane >> 2);
#pragma unroll
            for (int n = 0; n < 8; ++n) {
                const int c0 = bn + warp_n * 64 + n * 8 + (lane & 3) * 2;
                const float bx = __ldg(&bias[c0]), by = __ldg(&bias[c0 + 1]);
#pragma unroll
                for (int h = 0; h < 2; ++h) {
                    float vx = acc[m][n][h * 2 + 0] + bx;
                    float vy = acc[m][n][h * 2 + 1] + by;
                    vx = vx >= 0.f ? vx : a * vx;
                    vy = vy >= 0.f ? vy : a * vy;
                    __nv_bfloat16 hx = __float2bfloat16_rn(vx), hy = __float2bfloat16_rn(vy);
                    float rx = vx - __bfloat162float(hx), ry = vy - __bfloat162float(hy);
                    uint32_t hi = ((uint32_t)__bfloat16_as_ushort(hy) << 16) | __bfloat16_as_ushort(hx);
                    uint32_t lo = pack_bf16(rx, ry);
                    const size_t base = (size_t)(r0 + h * 8) * ldout + c0;
                    *(uint32_t*)&Aout[base]         = hi;
                    *(uint32_t*)&Aout[base + KKout] = lo;
                }
            }
        }
    } else {
        float* C = (float*)OutP;
#pragma unroll
        for (int m = 0; m < 2; ++m) {
            const int r0 = bm + warp_m * 32 + m * 16 + (lane >> 2);
#pragma unroll
            for (int n = 0; n < 8; ++n) {
                const int c0 = bn + warp_n * 64 + n * 8 + (lane & 3) * 2;
                const float bx = __ldg(&bias[c0]), by = __ldg(&bias[c0 + 1]);
                *(float2*)(C + (size_t)r0 * ldout + c0) =
                    make_float2(acc[m][n][0] + bx, acc[m][n][1] + by);
                *(float2*)(C + (size_t)(r0 + 8) * ldout + c0) =
                    make_float2(acc[m][n][2] + bx, acc[m][n][3] + by);
            }
        }
    }
}

// ---------------------------------------------------------------------------
// Fused prep: all weight hi/lo stacks + X hi/lo split + S.X  (one launch)
// ---------------------------------------------------------------------------
static __device__ __forceinline__ void split_unit(
    const float* __restrict__ src, __nv_bfloat16* __restrict__ dst,
    int ldb, int offH, int offL, int offH2, int K, int idx)
{
    const int per = K >> 2;
    const int row = idx / per;
    const int j   = (idx - row * per) << 2;
    float4 v = *(const float4*)(src + (size_t)row * K + j);
    __nv_bfloat16 h0 = __float2bfloat16_rn(v.x), h1 = __float2bfloat16_rn(v.y);
    __nv_bfloat16 h2 = __float2bfloat16_rn(v.z), h3 = __float2bfloat16_rn(v.w);
    uint2 hh;
    hh.x = ((uint32_t)__bfloat16_as_ushort(h1) << 16) | __bfloat16_as_ushort(h0);
    hh.y = ((uint32_t)__bfloat16_as_ushort(h3) << 16) | __bfloat16_as_ushort(h2);
    *(uint2*)(dst + (size_t)row * ldb + offH + j) = hh;
    if (offL >= 0) {
        uint2 ll;
        ll.x = pack_bf16(v.x - __bfloat162float(h0), v.y - __bfloat162float(h1));
        ll.y = pack_bf16(v.z - __bfloat162float(h2), v.w - __bfloat162float(h3));
        *(uint2*)(dst + (size_t)row * ldb + offL + j) = ll;
    }
    if (offH2 >= 0)
        *(uint2*)(dst + (size_t)row * ldb + offH2 + j) = hh;
}

__global__ void prep_all(const float* __restrict__ X, const float* __restrict__ ea,
                         const float* __restrict__ W_rel1, const float* __restrict__ W_root1,
                         const float* __restrict__ W_rel2, const float* __restrict__ W_root2,
                         const float* __restrict__ W_fc,
                         __nv_bfloat16* __restrict__ B1s, __nv_bfloat16* __restrict__ B2s,
                         __nv_bfloat16* __restrict__ Bfs,
                         __nv_bfloat16* __restrict__ A1, __nv_bfloat16* __restrict__ SA)
{
    const int b   = blockIdx.x;
    const int tid = threadIdx.x;

    if (b < 224) {   // weight prep
        if (b < 32)       split_unit(W_rel1,  B1s,  512,   0,  -1,  -1, 128, b * 256 + tid);
        else if (b < 64)  split_unit(W_root1, B1s,  512, 128, 256, 384, 128, (b - 32) * 256 + tid);
        else if (b < 128) split_unit(W_rel2,  B2s, 1024,   0,  -1,  -1, 256, (b - 64) * 256 + tid);
        else if (b < 192) split_unit(W_root2, B2s, 1024, 256, 512, 768, 256, (b - 128) * 256 + tid);
        else              split_unit(W_fc,    Bfs,  768,   0, 256, 512, 256, (b - 192) * 256 + tid);
        return;
    }

    // X prep: hi/lo split + window shift
    const int idx = (b - 224) * 256 + tid;      // 0 .. N*32
    const int row = idx >> 5;
    const int col = (idx & 31) << 2;
    const int t   = row & (LSEQ - 1);

    float4 v = *(const float4*)(X + (size_t)row * 128 + col);
    __nv_bfloat16 h0 = __float2bfloat16_rn(v.x), h1 = __float2bfloat16_rn(v.y);
    __nv_bfloat16 h2 = __float2bfloat16_rn(v.z), h3 = __float2bfloat16_rn(v.w);
    uint2 hh, ll;
    hh.x = ((uint32_t)__bfloat16_as_ushort(h1) << 16) | __bfloat16_as_ushort(h0);
    hh.y = ((uint32_t)__bfloat16_as_ushort(h3) << 16) | __bfloat16_as_ushort(h2);
    ll.x = pack_bf16(v.x - __bfloat162float(h0), v.y - __bfloat162float(h1));
    ll.y = pack_bf16(v.z - __bfloat162float(h2), v.w - __bfloat162float(h3));
    *(uint2*)(A1 + (size_t)row * 256 + col)       = hh;
    *(uint2*)(A1 + (size_t)row * 256 + 128 + col) = ll;

    const int starts[8] = {0, 2047, 4093, 6138, 8182, 10225, 12267, 14308};
    float4 s = make_float4(0.f, 0.f, 0.f, 0.f);
#pragma unroll
    for (int d = 1; d <= 8; ++d) {
        if (t >= d) {
            const float wd = __ldg(&ea[starts[d - 1]]);
            float4 xd = *(const float4*)(X + (size_t)(row - d) * 128 + col);
            s.x = fmaf(wd, xd.x, s.x); s.y = fmaf(wd, xd.y, s.y);
            s.z = fmaf(wd, xd.z, s.z); s.w = fmaf(wd, xd.w, s.w);
        }
    }
    uint2 so;
    so.x = pack_bf16(s.x, s.y);
    so.y = pack_bf16(s.z, s.w);
    *(uint2*)(SA + (size_t)row * 128 + col) = so;
}

// ---------------------------------------------------------------------------
// shift_h: SH[i,:] = sum_d w_d * Hh[i-d,:]   (Hh = hi half of [N, 512] layout)
// ---------------------------------------------------------------------------
__global__ void shift_h(const __nv_bfloat16* __restrict__ Hh, const float* __restrict__ ea,
                        __nv_bfloat16* __restrict__ SH)
{
    const int idx = blockIdx.x * blockDim.x + threadIdx.x;
    const int row = idx >> 6;
    const int col = (idx & 63) << 2;
    const int t   = row & (LSEQ - 1);

    const int starts[8] = {0, 2047, 4093, 6138, 8182, 10225, 12267, 14308};
    float4 s = make_float4(0.f, 0.f, 0.f, 0.f);
#pragma unroll
    for (int d = 1; d <= 8; ++d) {
        if (t >= d) {
            const float wd = __ldg(&ea[starts[d - 1]]);
            uint2 u = *(const uint2*)(Hh + (size_t)(row - d) * 512 + col);
            s.x = fmaf(wd, __bfloat162float(__ushort_as_bfloat16((ushort)(u.x & 0xFFFF))), s.x);
            s.y = fmaf(wd, __bfloat162float(__ushort_as_bfloat16((ushort)(u.x >> 16))),    s.y);
            s.z = fmaf(wd, __bfloat162float(__ushort_as_bfloat16((ushort)(u.y & 0xFFFF))), s.z);
            s.w = fmaf(wd, __bfloat162float(__ushort_as_bfloat16((ushort)(u.y >> 16))),    s.w);
        }
    }
    uint2 so;
    so.x = pack_bf16(s.x, s.y);
    so.y = pack_bf16(s.z, s.w);
    *(uint2*)(SH + (size_t)row * 256 + col) = so;
}

// ---------------------------------------------------------------------------
extern "C" void kernel_launch(void* const* d_in, const int* in_sizes, int n_in,
                              void* d_out, int out_size)
{
    const float* X       = (const float*)d_in[0];
    const float* W_rel1  = (const float*)d_in[1];
    const float* b_rel1  = (const float*)d_in[2];
    const float* W_root1 = (const float*)d_in[3];
    const float* W_rel2  = (const float*)d_in[4];
    const float* b_rel2  = (const float*)d_in[5];
    const float* W_root2 = (const float*)d_in[6];
    const float* a1      = (const float*)d_in[7];
    const float* a2      = (const float*)d_in[8];
    const float* W_fc    = (const float*)d_in[9];
    const float* b_fc    = (const float*)d_in[10];
    const float* ea      = (const float*)d_in[11];
    float*       out     = (float*)d_out;

    __nv_bfloat16 *A1, *A2, *A3, *SA, *SH, *B1s, *B2s, *Bfs;
    cudaGetSymbolAddress((void**)&A1,  g_A1);
    cudaGetSymbolAddress((void**)&A2,  g_A2);
    cudaGetSymbolAddress((void**)&A3,  g_A3);
    cudaGetSymbolAddress((void**)&SA,  g_SA);
    cudaGetSymbolAddress((void**)&SH,  g_SH);
    cudaGetSymbolAddress((void**)&B1s, g_B1s);
    cudaGetSymbolAddress((void**)&B2s, g_B2s);
    cudaGetSymbolAddress((void**)&Bfs, g_Bfs);

    constexpr int SMB = NSTG * STAGEB;   // 81920
    cudaFuncSetAttribute(gemm_mma<4, true>,  cudaFuncAttributeMaxDynamicSharedMemorySize, SMB);
    cudaFuncSetAttribute(gemm_mma<3, false>, cudaFuncAttributeMaxDynamicSharedMemorySize, SMB);

    // all prep in one launch
    prep_all<<<224 + NNODE * 32 / 256, 256>>>(X, ea, W_rel1, W_root1, W_rel2, W_root2, W_fc,
                                              B1s, B2s, Bfs, A1, SA);

    // Layer 1: H1 = prelu([S.X | Xh | Xh | Xl] @ [Wrel1h|Wroot1h|Wroot1l|Wroot1h]^T + b1)
    gemm_mma<4, true><<<dim3(2, 256), 256, SMB>>>(SA, A1, A1, A1 + 128,
                                                  128, 256, 256, 256,
                                                  B1s, b_rel1, a1, A2, 128, 512);
    // S.H1
    shift_h<<<NNODE * 64 / 256, 256>>>(A2, ea, SH);

    // Layer 2
    gemm_mma<4, true><<<dim3(2, 256), 256, SMB>>>(SH, A2, A2, A2 + 256,
                                                  256, 512, 512, 512,
                                                  B2s, b_rel2, a2, A3, 256, 512);
    // FC: out = [H2h|H2h|H2l] @ [Wfch|Wfcl|Wfch]^T + b_fc
    gemm_mma<3, false><<<dim3(1, 256), 256, SMB>>>(A3, A3, A3 + 256, A3,
                                                   512, 512, 512, 512,
                                                   Bfs, b_fc, nullptr, out, 256, 128);
}

// round 6
// speedup vs baseline: 2.6794x; 1.0492x over previous
#include <cuda_runtime.h>
#include <cuda_bf16.h>
#include <cstdint>

#define NNODE 32768
#define LSEQ  2048

// ---------------- device scratch (no allocation allowed) -------------------
__device__ __align__(16) __nv_bfloat16 g_A1 [NNODE * 256];   // [N, 2*128]  X hi|lo
__device__ __align__(16) __nv_bfloat16 g_A2 [NNODE * 512];   // [N, 2*256]  H1 hi|lo
__device__ __align__(16) __nv_bfloat16 g_A3 [NNODE * 512];   // [N, 2*256]  H2 hi|lo
__device__ __align__(16) __nv_bfloat16 g_SA [NNODE * 128];   // [N, 128]  S.X
__device__ __align__(16) __nv_bfloat16 g_SH [NNODE * 256];   // [N, 256]  S.H1
__device__ __align__(16) __nv_bfloat16 g_B1s[256 * 512];     // [Wrel1h|Wroot1h|Wroot1l|Wroot1h]
__device__ __align__(16) __nv_bfloat16 g_B2s[256 * 1024];    // same, K=256
__device__ __align__(16) __nv_bfloat16 g_Bfs[128 * 768];     // [Wfch|Wfcl|Wfch]

// ---------------- PTX helpers ----------------------------------------------
static __device__ __forceinline__ void cp16(uint32_t dst, const void* src) {
    asm volatile("cp.async.cg.shared.global [%0], [%1], 16;" :: "r"(dst), "l"(src) : "memory");
}
static __device__ __forceinline__ void cp_commit() {
    asm volatile("cp.async.commit_group;" ::: "memory");
}

#define LDSM4(r0, r1, r2, r3, a) \
    asm volatile("ldmatrix.sync.aligned.m8n8.x4.shared.b16 {%0,%1,%2,%3}, [%4];" \
                 : "=r"(r0), "=r"(r1), "=r"(r2), "=r"(r3) : "r"(a))

#define MMA16816(d, a, b0, b1) \
    asm volatile("mma.sync.aligned.m16n8k16.row.col.f32.bf16.bf16.f32 " \
                 "{%0,%1,%2,%3}, {%4,%5,%6,%7}, {%8,%9}, {%0,%1,%2,%3};" \
                 : "+f"((d)[0]), "+f"((d)[1]), "+f"((d)[2]), "+f"((d)[3]) \
                 : "r"((a)[0]), "r"((a)[1]), "r"((a)[2]), "r"((a)[3]), \
                   "r"(b0), "r"(b1))

static __device__ __forceinline__ uint32_t pack_bf16(float x, float y) {
    __nv_bfloat16 h0 = __float2bfloat16_rn(x), h1 = __float2bfloat16_rn(y);
    return ((uint32_t)__bfloat16_as_ushort(h1) << 16) | __bfloat16_as_ushort(h0);
}

// ---------------------------------------------------------------------------
// Segmented-K bf16 HMMA GEMM, virtual K = NSEG*KK, 4-stage cp.async pipeline
// + register double-buffered mainloop (CUTLASS-style).
// CTA tile 128x128, BK=32, 8 warps (4M x 2N).
// ---------------------------------------------------------------------------
#define ROWB   80
#define TILEB  (128 * ROWB)          // 10240
#define STAGEB (2 * TILEB)           // 20480
#define NSTG   4

struct Frag { uint32_t a[2][4]; uint32_t b[4][4]; };

template <int NSEG, bool LAYER>
__global__ __launch_bounds__(256, 2)
void gemm_mma(const __nv_bfloat16* __restrict__ A0, const __nv_bfloat16* __restrict__ A1p,
              const __nv_bfloat16* __restrict__ A2p, const __nv_bfloat16* __restrict__ A3p,
              int l0, int l1, int l2, int l3,
              const __nv_bfloat16* __restrict__ Bs,
              const float* __restrict__ bias, const float* __restrict__ slope,
              void* __restrict__ OutP, int KK, int ldout)
{
    extern __shared__ __align__(16) char smem[];   // NSTG * STAGEB = 81920
    const uint32_t sb = (uint32_t)__cvta_generic_to_shared(smem);

    const int tid    = threadIdx.x;
    const int lane   = tid & 31;
    const int wid    = tid >> 5;
    const int warp_m = wid & 3;
    const int warp_n = wid >> 2;
    const int bm     = blockIdx.y * 128;
    const int bn     = blockIdx.x * 128;
    const int ldb    = NSEG * KK;
    const int nkk    = KK >> 5;
    const int nc     = NSEG * nkk;

    // per-thread load geometry (2 16B units for A, 2 for B)
    int rA[2], qA[2];
    const __nv_bfloat16* bsrc[2]; uint32_t adst[2], bdst[2];
#pragma unroll
    for (int i = 0; i < 2; ++i) {
        int u = i * 256 + tid, r = u >> 2, q = u & 3;
        rA[i] = r; qA[i] = q;
        adst[i] = sb + (uint32_t)(r * ROWB + q * 16);
        bsrc[i] = Bs + (size_t)(bn + r) * ldb + q * 8;
        bdst[i] = sb + TILEB + (uint32_t)(r * ROWB + q * 16);
    }

    auto issue = [&](int c) {
        if (c < nc) {
            int seg;
            if (NSEG == 4) seg = (c >= 3 * nkk) ? 3 : (c >= 2 * nkk) ? 2 : (c >= nkk) ? 1 : 0;
            else           seg = (c >= 2 * nkk) ? 2 : (c >= nkk) ? 1 : 0;
            const __nv_bfloat16* ab; int al;
            if      (seg == 0) { ab = A0;  al = l0; }
            else if (seg == 1) { ab = A1p; al = l1; }
            else if (seg == 2) { ab = A2p; al = l2; }
            else               { ab = A3p; al = l3; }
            const __nv_bfloat16* arow = ab + (size_t)bm * al + (c - seg * nkk) * 32;
            uint32_t st = (uint32_t)(c & (NSTG - 1)) * STAGEB;
#pragma unroll
            for (int i = 0; i < 2; ++i) cp16(adst[i] + st, arow + (size_t)rA[i] * al + qA[i] * 8);
#pragma unroll
            for (int i = 0; i < 2; ++i) cp16(bdst[i] + st, bsrc[i] + c * 32);
        }
        cp_commit();   // dummy groups keep wait_group counting valid
    };

    // ldmatrix addresses (stage/k-step invariant)
    uint32_t aAddr[2];
#pragma unroll
    for (int m = 0; m < 2; ++m) {
        int row = warp_m * 32 + m * 16 + (lane & 15);
        aAddr[m] = sb + (uint32_t)(row * ROWB + (lane >> 4) * 16);
    }
    uint32_t bAddr[4];
#pragma unroll
    for (int p = 0; p < 4; ++p) {
        int row = warp_n * 64 + (2 * p + (lane >> 4)) * 8 + (lane & 7);
        bAddr[p] = sb + TILEB + (uint32_t)(row * ROWB + ((lane >> 3) & 1) * 16);
    }

    auto ldsm_frag = [&](Frag& f, uint32_t off) {
#pragma unroll
        for (int m = 0; m < 2; ++m)
            LDSM4(f.a[m][0], f.a[m][1], f.a[m][2], f.a[m][3], aAddr[m] + off);
#pragma unroll
        for (int p = 0; p < 4; ++p)
            LDSM4(f.b[p][0], f.b[p][1], f.b[p][2], f.b[p][3], bAddr[p] + off);
    };

    float acc[2][8][4];
#pragma unroll
    for (int m = 0; m < 2; ++m)
#pragma unroll
        for (int n = 0; n < 8; ++n)
#pragma unroll
            for (int j = 0; j < 4; ++j) acc[m][n][j] = 0.0f;

    auto mma_frag = [&](const Frag& f) {
#pragma unroll
        for (int m = 0; m < 2; ++m)
#pragma unroll
            for (int n = 0; n < 8; ++n)
                MMA16816(acc[m][n], f.a[m], f.b[n >> 1][(n & 1) * 2], f.b[n >> 1][(n & 1) * 2 + 1]);
    };

    // prologue: stages 0..2 in flight, chunk 0 resident, frag0 primed
    issue(0); issue(1); issue(2);
    asm volatile("cp.async.wait_group 2;" ::: "memory");
    __syncthreads();

    Frag f0, f1;
    ldsm_frag(f0, 0);                       // chunk 0, ks 0

    for (int s = 0; s < nc; ++s) {
        const uint32_t st = (uint32_t)(s & (NSTG - 1)) * STAGEB;

        // ---- ks = 0: load ks1 frags, refill pipeline, MMA frag0 ----
        ldsm_frag(f1, st + 32);
        issue(s + 3);
        mma_frag(f0);

        // ---- ks = 1: advance smem pipeline, prime next chunk's ks0, MMA frag1
        asm volatile("cp.async.wait_group 2;" ::: "memory");   // chunk s+1 resident
        __syncthreads();                                        // stage (s)&3 free for reuse
        ldsm_frag(f0, (uint32_t)((s + 1) & (NSTG - 1)) * STAGEB);  // next chunk ks0 (junk on last iter, in-bounds)
        mma_frag(f1);
    }

    // ---- epilogue ----------------------------------------------------------
    if (LAYER) {
        __nv_bfloat16* Aout = (__nv_bfloat16*)OutP;
        const int KKout = ldout >> 1;
        const float a = __ldg(slope);
#pragma unroll
        for (int m = 0; m < 2; ++m) {
            const int r0 = bm + warp_m * 32 + m * 16 + (lane >> 2);
#pragma unroll
            for (int n = 0; n < 8; ++n) {
                const int c0 = bn + warp_n * 64 + n * 8 + (lane & 3) * 2;
                const float bx = __ldg(&bias[c0]), by = __ldg(&bias[c0 + 1]);
#pragma unroll
                for (int h = 0; h < 2; ++h) {
                    float vx = acc[m][n][h * 2 + 0] + bx;
                    float vy = acc[m][n][h * 2 + 1] + by;
                    vx = vx >= 0.f ? vx : a * vx;
                    vy = vy >= 0.f ? vy : a * vy;
                    __nv_bfloat16 hx = __float2bfloat16_rn(vx), hy = __float2bfloat16_rn(vy);
                    float rx = vx - __bfloat162float(hx), ry = vy - __bfloat162float(hy);
                    uint32_t hi = ((uint32_t)__bfloat16_as_ushort(hy) << 16) | __bfloat16_as_ushort(hx);
                    uint32_t lo = pack_bf16(rx, ry);
                    const size_t base = (size_t)(r0 + h * 8) * ldout + c0;
                    *(uint32_t*)&Aout[base]         = hi;
                    *(uint32_t*)&Aout[base + KKout] = lo;
                }
            }
        }
    } else {
        float* C = (float*)OutP;
#pragma unroll
        for (int m = 0; m < 2; ++m) {
            const int r0 = bm + warp_m * 32 + m * 16 + (lane >> 2);
#pragma unroll
            for (int n = 0; n < 8; ++n) {
                const int c0 = bn + warp_n * 64 + n * 8 + (lane & 3) * 2;
                const float bx = __ldg(&bias[c0]), by = __ldg(&bias[c0 + 1]);
                *(float2*)(C + (size_t)r0 * ldout + c0) =
                    make_float2(acc[m][n][0] + bx, acc[m][n][1] + by);
                *(float2*)(C + (size_t)(r0 + 8) * ldout + c0) =
                    make_float2(acc[m][n][2] + bx, acc[m][n][3] + by);
            }
        }
    }
}

// ---------------------------------------------------------------------------
// Fused prep: all weight hi/lo stacks + X hi/lo split + S.X  (one launch)
// ---------------------------------------------------------------------------
static __device__ __forceinline__ void split_unit(
    const float* __restrict__ src, __nv_bfloat16* __restrict__ dst,
    int ldb, int offH, int offL, int offH2, int K, int idx)
{
    const int per = K >> 2;
    const int row = idx / per;
    const int j   = (idx - row * per) << 2;
    float4 v = *(const float4*)(src + (size_t)row * K + j);
    __nv_bfloat16 h0 = __float2bfloat16_rn(v.x), h1 = __float2bfloat16_rn(v.y);
    __nv_bfloat16 h2 = __float2bfloat16_rn(v.z), h3 = __float2bfloat16_rn(v.w);
    uint2 hh;
    hh.x = ((uint32_t)__bfloat16_as_ushort(h1) << 16) | __bfloat16_as_ushort(h0);
    hh.y = ((uint32_t)__bfloat16_as_ushort(h3) << 16) | __bfloat16_as_ushort(h2);
    *(uint2*)(dst + (size_t)row * ldb + offH + j) = hh;
    if (offL >= 0) {
        uint2 ll;
        ll.x = pack_bf16(v.x - __bfloat162float(h0), v.y - __bfloat162float(h1));
        ll.y = pack_bf16(v.z - __bfloat162float(h2), v.w - __bfloat162float(h3));
        *(uint2*)(dst + (size_t)row * ldb + offL + j) = ll;
    }
    if (offH2 >= 0)
        *(uint2*)(dst + (size_t)row * ldb + offH2 + j) = hh;
}

__global__ void prep_all(const float* __restrict__ X, const float* __restrict__ ea,
                         const float* __restrict__ W_rel1, const float* __restrict__ W_root1,
                         const float* __restrict__ W_rel2, const float* __restrict__ W_root2,
                         const float* __restrict__ W_fc,
                         __nv_bfloat16* __restrict__ B1s, __nv_bfloat16* __restrict__ B2s,
                         __nv_bfloat16* __restrict__ Bfs,
                         __nv_bfloat16* __restrict__ A1, __nv_bfloat16* __restrict__ SA)
{
    const int b   = blockIdx.x;
    const int tid = threadIdx.x;

    if (b < 224) {   // weight prep
        if (b < 32)       split_unit(W_rel1,  B1s,  512,   0,  -1,  -1, 128, b * 256 + tid);
        else if (b < 64)  split_unit(W_root1, B1s,  512, 128, 256, 384, 128, (b - 32) * 256 + tid);
        else if (b < 128) split_unit(W_rel2,  B2s, 1024,   0,  -1,  -1, 256, (b - 64) * 256 + tid);
        else if (b < 192) split_unit(W_root2, B2s, 1024, 256, 512, 768, 256, (b - 128) * 256 + tid);
        else              split_unit(W_fc,    Bfs,  768,   0, 256, 512, 256, (b - 192) * 256 + tid);
        return;
    }

    // X prep: hi/lo split + window shift
    const int idx = (b - 224) * 256 + tid;      // 0 .. N*32
    const int row = idx >> 5;
    const int col = (idx & 31) << 2;
    const int t   = row & (LSEQ - 1);

    float4 v = *(const float4*)(X + (size_t)row * 128 + col);
    __nv_bfloat16 h0 = __float2bfloat16_rn(v.x), h1 = __float2bfloat16_rn(v.y);
    __nv_bfloat16 h2 = __float2bfloat16_rn(v.z), h3 = __float2bfloat16_rn(v.w);
    uint2 hh, ll;
    hh.x = ((uint32_t)__bfloat16_as_ushort(h1) << 16) | __bfloat16_as_ushort(h0);
    hh.y = ((uint32_t)__bfloat16_as_ushort(h3) << 16) | __bfloat16_as_ushort(h2);
    ll.x = pack_bf16(v.x - __bfloat162float(h0), v.y - __bfloat162float(h1));
    ll.y = pack_bf16(v.z - __bfloat162float(h2), v.w - __bfloat162float(h3));
    *(uint2*)(A1 + (size_t)row * 256 + col)       = hh;
    *(uint2*)(A1 + (size_t)row * 256 + 128 + col) = ll;

    const int starts[8] = {0, 2047, 4093, 6138, 8182, 10225, 12267, 14308};
    float4 s = make_float4(0.f, 0.f, 0.f, 0.f);
#pragma unroll
    for (int d = 1; d <= 8; ++d) {
        if (t >= d) {
            const float wd = __ldg(&ea[starts[d - 1]]);
            float4 xd = *(const float4*)(X + (size_t)(row - d) * 128 + col);
            s.x = fmaf(wd, xd.x, s.x); s.y = fmaf(wd, xd.y, s.y);
            s.z = fmaf(wd, xd.z, s.z); s.w = fmaf(wd, xd.w, s.w);
        }
    }
    uint2 so;
    so.x = pack_bf16(s.x, s.y);
    so.y = pack_bf16(s.z, s.w);
    *(uint2*)(SA + (size_t)row * 128 + col) = so;
}

// ---------------------------------------------------------------------------
// shift_h: SH[i,:] = sum_d w_d * Hh[i-d,:]   (Hh = hi half of [N, 512] layout)
// ---------------------------------------------------------------------------
__global__ void shift_h(const __nv_bfloat16* __restrict__ Hh, const float* __restrict__ ea,
                        __nv_bfloat16* __restrict__ SH)
{
    const int idx = blockIdx.x * blockDim.x + threadIdx.x;
    const int row = idx >> 6;
    const int col = (idx & 63) << 2;
    const int t   = row & (LSEQ - 1);

    const int starts[8] = {0, 2047, 4093, 6138, 8182, 10225, 12267, 14308};
    float4 s = make_float4(0.f, 0.f, 0.f, 0.f);
#pragma unroll
    for (int d = 1; d <= 8; ++d) {
        if (t >= d) {
            const float wd = __ldg(&ea[starts[d - 1]]);
            uint2 u = *(const uint2*)(Hh + (size_t)(row - d) * 512 + col);
            s.x = fmaf(wd, __bfloat162float(__ushort_as_bfloat16((ushort)(u.x & 0xFFFF))), s.x);
            s.y = fmaf(wd, __bfloat162float(__ushort_as_bfloat16((ushort)(u.x >> 16))),    s.y);
            s.z = fmaf(wd, __bfloat162float(__ushort_as_bfloat16((ushort)(u.y & 0xFFFF))), s.z);
            s.w = fmaf(wd, __bfloat162float(__ushort_as_bfloat16((ushort)(u.y >> 16))),    s.w);
        }
    }
    uint2 so;
    so.x = pack_bf16(s.x, s.y);
    so.y = pack_bf16(s.z, s.w);
    *(uint2*)(SH + (size_t)row * 256 + col) = so;
}

// ---------------------------------------------------------------------------
extern "C" void kernel_launch(void* const* d_in, const int* in_sizes, int n_in,
                              void* d_out, int out_size)
{
    const float* X       = (const float*)d_in[0];
    const float* W_rel1  = (const float*)d_in[1];
    const float* b_rel1  = (const float*)d_in[2];
    const float* W_root1 = (const float*)d_in[3];
    const float* W_rel2  = (const float*)d_in[4];
    const float* b_rel2  = (const float*)d_in[5];
    const float* W_root2 = (const float*)d_in[6];
    const float* a1      = (const float*)d_in[7];
    const float* a2      = (const float*)d_in[8];
    const float* W_fc    = (const float*)d_in[9];
    const float* b_fc    = (const float*)d_in[10];
    const float* ea      = (const float*)d_in[11];
    float*       out     = (float*)d_out;

    __nv_bfloat16 *A1, *A2, *A3, *SA, *SH, *B1s, *B2s, *Bfs;
    cudaGetSymbolAddress((void**)&A1,  g_A1);
    cudaGetSymbolAddress((void**)&A2,  g_A2);
    cudaGetSymbolAddress((void**)&A3,  g_A3);
    cudaGetSymbolAddress((void**)&SA,  g_SA);
    cudaGetSymbolAddress((void**)&SH,  g_SH);
    cudaGetSymbolAddress((void**)&B1s, g_B1s);
    cudaGetSymbolAddress((void**)&B2s, g_B2s);
    cudaGetSymbolAddress((void**)&Bfs, g_Bfs);

    constexpr int SMB = NSTG * STAGEB;   // 81920
    cudaFuncSetAttribute(gemm_mma<4, true>,  cudaFuncAttributeMaxDynamicSharedMemorySize, SMB);
    cudaFuncSetAttribute(gemm_mma<3, false>, cudaFuncAttributeMaxDynamicSharedMemorySize, SMB);

    // all prep in one launch
    prep_all<<<224 + NNODE * 32 / 256, 256>>>(X, ea, W_rel1, W_root1, W_rel2, W_root2, W_fc,
                                              B1s, B2s, Bfs, A1, SA);

    // Layer 1: H1 = prelu([S.X | Xh | Xh | Xl] @ [Wrel1h|Wroot1h|Wroot1l|Wroot1h]^T + b1)
    gemm_mma<4, true><<<dim3(2, 256), 256, SMB>>>(SA, A1, A1, A1 + 128,
                                                  128, 256, 256, 256,
                                                  B1s, b_rel1, a1, A2, 128, 512);
    // S.H1
    shift_h<<<NNODE * 64 / 256, 256>>>(A2, ea, SH);

    // Layer 2
    gemm_mma<4, true><<<dim3(2, 256), 256, SMB>>>(SH, A2, A2, A2 + 256,
                                                  256, 512, 512, 512,
                                                  B2s, b_rel2, a2, A3, 256, 512);
    // FC: out = [H2h|H2h|H2l] @ [Wfch|Wfcl|Wfch]^T + b_fc
    gemm_mma<3, false><<<dim3(1, 256), 256, SMB>>>(A3, A3, A3 + 256, A3,
                                                   512, 512, 512, 512,
                                                   Bfs, b_fc, nullptr, out, 256, 128);
}

// round 7
// speedup vs baseline: 3.0013x; 1.1201x over previous
#include <cuda_runtime.h>
#include <cuda_bf16.h>
#include <cstdint>

#define NNODE 32768
#define LSEQ  2048

// ---------------- device scratch (no allocation allowed) -------------------
__device__ __align__(16) __nv_bfloat16 g_A1 [NNODE * 256];   // [N, 2*128]  X hi|lo
__device__ __align__(16) __nv_bfloat16 g_A2 [NNODE * 512];   // [N, 2*256]  H1 hi|lo
__device__ __align__(16) __nv_bfloat16 g_A3 [NNODE * 512];   // [N, 2*256]  H2 hi|lo
__device__ __align__(16) __nv_bfloat16 g_SA [NNODE * 128];   // [N, 128]  S.X
__device__ __align__(16) __nv_bfloat16 g_SH [NNODE * 256];   // [N, 256]  S.H1
__device__ __align__(16) __nv_bfloat16 g_B1s[256 * 512];     // [Wrel1h|Wroot1h|Wroot1l|Wroot1h]
__device__ __align__(16) __nv_bfloat16 g_B2s[256 * 1024];    // same, K=256
__device__ __align__(16) __nv_bfloat16 g_Bfs[128 * 768];     // [Wfch|Wfcl|Wfch]

// ---------------- PTX helpers ----------------------------------------------
static __device__ __forceinline__ void cp16(uint32_t dst, const void* src) {
    asm volatile("cp.async.cg.shared.global [%0], [%1], 16;" :: "r"(dst), "l"(src) : "memory");
}
static __device__ __forceinline__ void cp_commit() {
    asm volatile("cp.async.commit_group;" ::: "memory");
}

#define LDSM4(r0, r1, r2, r3, a) \
    asm volatile("ldmatrix.sync.aligned.m8n8.x4.shared.b16 {%0,%1,%2,%3}, [%4];" \
                 : "=r"(r0), "=r"(r1), "=r"(r2), "=r"(r3) : "r"(a))

#define MMA16816(d, a, b0, b1) \
    asm volatile("mma.sync.aligned.m16n8k16.row.col.f32.bf16.bf16.f32 " \
                 "{%0,%1,%2,%3}, {%4,%5,%6,%7}, {%8,%9}, {%0,%1,%2,%3};" \
                 : "+f"((d)[0]), "+f"((d)[1]), "+f"((d)[2]), "+f"((d)[3]) \
                 : "r"((a)[0]), "r"((a)[1]), "r"((a)[2]), "r"((a)[3]), \
                   "r"(b0), "r"(b1))

static __device__ __forceinline__ uint32_t pack_bf16(float x, float y) {
    __nv_bfloat16 h0 = __float2bfloat16_rn(x), h1 = __float2bfloat16_rn(y);
    return ((uint32_t)__bfloat16_as_ushort(h1) << 16) | __bfloat16_as_ushort(h0);
}

// ---------------------------------------------------------------------------
// Segmented-K bf16 HMMA GEMM, virtual K = NSEG*KK, 4-stage cp.async pipeline
// + register double-buffered mainloop.
// CTA tile 256x128, 8 warps (4M x 2N), warp tile 64x64. 1 CTA/SM.
// ---------------------------------------------------------------------------
#define ROWB   80
#define ATILE  (256 * ROWB)          // 20480
#define BTILE  (128 * ROWB)          // 10240
#define STAGEB (ATILE + BTILE)       // 30720
#define NSTG   4

struct Frag { uint32_t a[4][4]; uint32_t b[4][4]; };

template <int NSEG, bool LAYER>
__global__ __launch_bounds__(256, 1)
void gemm_mma(const __nv_bfloat16* __restrict__ A0, const __nv_bfloat16* __restrict__ A1p,
              const __nv_bfloat16* __restrict__ A2p, const __nv_bfloat16* __restrict__ A3p,
              int l0, int l1, int l2, int l3,
              const __nv_bfloat16* __restrict__ Bs,
              const float* __restrict__ bias, const float* __restrict__ slope,
              void* __restrict__ OutP, int KK, int ldout)
{
    extern __shared__ __align__(16) char smem[];   // NSTG * STAGEB = 122880
    const uint32_t sb = (uint32_t)__cvta_generic_to_shared(smem);

    const int tid    = threadIdx.x;
    const int lane   = tid & 31;
    const int wid    = tid >> 5;
    const int warp_m = wid & 3;          // 0..3 -> 64-row block
    const int warp_n = wid >> 2;         // 0..1 -> 64-col block
    const int bm     = blockIdx.y * 256;
    const int bn     = blockIdx.x * 128;
    const int ldb    = NSEG * KK;
    const int nkk    = KK >> 5;
    const int nc     = NSEG * nkk;

    // per-thread load geometry: 4 16B units for A (256 rows), 2 for B (128 rows)
    int rA[4], qA[4];
    const __nv_bfloat16* bsrc[2]; uint32_t adst[4], bdst[2];
#pragma unroll
    for (int i = 0; i < 4; ++i) {
        int u = i * 256 + tid, r = u >> 2, q = u & 3;
        rA[i] = r; qA[i] = q;
        adst[i] = sb + (uint32_t)(r * ROWB + q * 16);
    }
#pragma unroll
    for (int i = 0; i < 2; ++i) {
        int u = i * 256 + tid, r = u >> 2, q = u & 3;
        bsrc[i] = Bs + (size_t)(bn + r) * ldb + q * 8;
        bdst[i] = sb + ATILE + (uint32_t)(r * ROWB + q * 16);
    }

    auto issue = [&](int c) {
        if (c < nc) {
            int seg;
            if (NSEG == 4) seg = (c >= 3 * nkk) ? 3 : (c >= 2 * nkk) ? 2 : (c >= nkk) ? 1 : 0;
            else           seg = (c >= 2 * nkk) ? 2 : (c >= nkk) ? 1 : 0;
            const __nv_bfloat16* ab; int al;
            if      (seg == 0) { ab = A0;  al = l0; }
            else if (seg == 1) { ab = A1p; al = l1; }
            else if (seg == 2) { ab = A2p; al = l2; }
            else               { ab = A3p; al = l3; }
            const __nv_bfloat16* arow = ab + (size_t)bm * al + (c - seg * nkk) * 32;
            uint32_t st = (uint32_t)(c & (NSTG - 1)) * STAGEB;
#pragma unroll
            for (int i = 0; i < 4; ++i) cp16(adst[i] + st, arow + (size_t)rA[i] * al + qA[i] * 8);
#pragma unroll
            for (int i = 0; i < 2; ++i) cp16(bdst[i] + st, bsrc[i] + c * 32);
        }
        cp_commit();   // dummy groups keep wait_group counting valid
    };

    // ldmatrix addresses (stage/k-step invariant)
    uint32_t aAddr[4];
#pragma unroll
    for (int m = 0; m < 4; ++m) {
        int row = warp_m * 64 + m * 16 + (lane & 15);
        aAddr[m] = sb + (uint32_t)(row * ROWB + (lane >> 4) * 16);
    }
    uint32_t bAddr[4];
#pragma unroll
    for (int p = 0; p < 4; ++p) {
        int row = warp_n * 64 + (2 * p + (lane >> 4)) * 8 + (lane & 7);
        bAddr[p] = sb + ATILE + (uint32_t)(row * ROWB + ((lane >> 3) & 1) * 16);
    }

    auto ldsm_frag = [&](Frag& f, uint32_t off) {
#pragma unroll
        for (int m = 0; m < 4; ++m)
            LDSM4(f.a[m][0], f.a[m][1], f.a[m][2], f.a[m][3], aAddr[m] + off);
#pragma unroll
        for (int p = 0; p < 4; ++p)
            LDSM4(f.b[p][0], f.b[p][1], f.b[p][2], f.b[p][3], bAddr[p] + off);
    };

    float acc[4][8][4];
#pragma unroll
    for (int m = 0; m < 4; ++m)
#pragma unroll
        for (int n = 0; n < 8; ++n)
#pragma unroll
            for (int j = 0; j < 4; ++j) acc[m][n][j] = 0.0f;

    auto mma_frag = [&](const Frag& f) {
#pragma unroll
        for (int m = 0; m < 4; ++m)
#pragma unroll
            for (int n = 0; n < 8; ++n)
                MMA16816(acc[m][n], f.a[m], f.b[n >> 1][(n & 1) * 2], f.b[n >> 1][(n & 1) * 2 + 1]);
    };

    // prologue: stages 0..2 in flight, chunk 0 resident, frag0 primed
    issue(0); issue(1); issue(2);
    asm volatile("cp.async.wait_group 2;" ::: "memory");
    __syncthreads();

    Frag f0, f1;
    ldsm_frag(f0, 0);                       // chunk 0, ks 0

    for (int s = 0; s < nc; ++s) {
        const uint32_t st = (uint32_t)(s & (NSTG - 1)) * STAGEB;

        // ---- ks = 0: load ks1 frags, refill pipeline, MMA frag0 ----
        ldsm_frag(f1, st + 32);
        issue(s + 3);
        mma_frag(f0);

        // ---- ks = 1: advance smem pipeline, prime next chunk's ks0, MMA frag1
        asm volatile("cp.async.wait_group 2;" ::: "memory");   // chunk s+1 resident
        __syncthreads();
        ldsm_frag(f0, (uint32_t)((s + 1) & (NSTG - 1)) * STAGEB);  // junk on last iter, in-bounds
        mma_frag(f1);
    }

    // ---- epilogue ----------------------------------------------------------
    if (LAYER) {
        __nv_bfloat16* Aout = (__nv_bfloat16*)OutP;
        const int KKout = ldout >> 1;
        const float a = __ldg(slope);
#pragma unroll
        for (int m = 0; m < 4; ++m) {
            const int r0 = bm + warp_m * 64 + m * 16 + (lane >> 2);
#pragma unroll
            for (int n = 0; n < 8; ++n) {
                const int c0 = bn + warp_n * 64 + n * 8 + (lane & 3) * 2;
                const float bx = __ldg(&bias[c0]), by = __ldg(&bias[c0 + 1]);
#pragma unroll
                for (int h = 0; h < 2; ++h) {
                    float vx = acc[m][n][h * 2 + 0] + bx;
                    float vy = acc[m][n][h * 2 + 1] + by;
                    vx = vx >= 0.f ? vx : a * vx;
                    vy = vy >= 0.f ? vy : a * vy;
                    __nv_bfloat16 hx = __float2bfloat16_rn(vx), hy = __float2bfloat16_rn(vy);
                    float rx = vx - __bfloat162float(hx), ry = vy - __bfloat162float(hy);
                    uint32_t hi = ((uint32_t)__bfloat16_as_ushort(hy) << 16) | __bfloat16_as_ushort(hx);
                    uint32_t lo = pack_bf16(rx, ry);
                    const size_t base = (size_t)(r0 + h * 8) * ldout + c0;
                    *(uint32_t*)&Aout[base]         = hi;
                    *(uint32_t*)&Aout[base + KKout] = lo;
                }
            }
        }
    } else {
        float* C = (float*)OutP;
#pragma unroll
        for (int m = 0; m < 4; ++m) {
            const int r0 = bm + warp_m * 64 + m * 16 + (lane >> 2);
#pragma unroll
            for (int n = 0; n < 8; ++n) {
                const int c0 = bn + warp_n * 64 + n * 8 + (lane & 3) * 2;
                const float bx = __ldg(&bias[c0]), by = __ldg(&bias[c0 + 1]);
                *(float2*)(C + (size_t)r0 * ldout + c0) =
                    make_float2(acc[m][n][0] + bx, acc[m][n][1] + by);
                *(float2*)(C + (size_t)(r0 + 8) * ldout + c0) =
                    make_float2(acc[m][n][2] + bx, acc[m][n][3] + by);
            }
        }
    }
}

// ---------------------------------------------------------------------------
// Fused prep: all weight hi/lo stacks + X hi/lo split + S.X  (one launch)
// ---------------------------------------------------------------------------
static __device__ __forceinline__ void split_unit(
    const float* __restrict__ src, __nv_bfloat16* __restrict__ dst,
    int ldb, int offH, int offL, int offH2, int K, int idx)
{
    const int per = K >> 2;
    const int row = idx / per;
    const int j   = (idx - row * per) << 2;
    float4 v = *(const float4*)(src + (size_t)row * K + j);
    __nv_bfloat16 h0 = __float2bfloat16_rn(v.x), h1 = __float2bfloat16_rn(v.y);
    __nv_bfloat16 h2 = __float2bfloat16_rn(v.z), h3 = __float2bfloat16_rn(v.w);
    uint2 hh;
    hh.x = ((uint32_t)__bfloat16_as_ushort(h1) << 16) | __bfloat16_as_ushort(h0);
    hh.y = ((uint32_t)__bfloat16_as_ushort(h3) << 16) | __bfloat16_as_ushort(h2);
    *(uint2*)(dst + (size_t)row * ldb + offH + j) = hh;
    if (offL >= 0) {
        uint2 ll;
        ll.x = pack_bf16(v.x - __bfloat162float(h0), v.y - __bfloat162float(h1));
        ll.y = pack_bf16(v.z - __bfloat162float(h2), v.w - __bfloat162float(h3));
        *(uint2*)(dst + (size_t)row * ldb + offL + j) = ll;
    }
    if (offH2 >= 0)
        *(uint2*)(dst + (size_t)row * ldb + offH2 + j) = hh;
}

__global__ void prep_all(const float* __restrict__ X, const float* __restrict__ ea,
                         const float* __restrict__ W_rel1, const float* __restrict__ W_root1,
                         const float* __restrict__ W_rel2, const float* __restrict__ W_root2,
                         const float* __restrict__ W_fc,
                         __nv_bfloat16* __restrict__ B1s, __nv_bfloat16* __restrict__ B2s,
                         __nv_bfloat16* __restrict__ Bfs,
                         __nv_bfloat16* __restrict__ A1, __nv_bfloat16* __restrict__ SA)
{
    const int b   = blockIdx.x;
    const int tid = threadIdx.x;

    if (b < 224) {   // weight prep
        if (b < 32)       split_unit(W_rel1,  B1s,  512,   0,  -1,  -1, 128, b * 256 + tid);
        else if (b < 64)  split_unit(W_root1, B1s,  512, 128, 256, 384, 128, (b - 32) * 256 + tid);
        else if (b < 128) split_unit(W_rel2,  B2s, 1024,   0,  -1,  -1, 256, (b - 64) * 256 + tid);
        else if (b < 192) split_unit(W_root2, B2s, 1024, 256, 512, 768, 256, (b - 128) * 256 + tid);
        else              split_unit(W_fc,    Bfs,  768,   0, 256, 512, 256, (b - 192) * 256 + tid);
        return;
    }

    // X prep: hi/lo split + window shift
    const int idx = (b - 224) * 256 + tid;      // 0 .. N*32
    const int row = idx >> 5;
    const int col = (idx & 31) << 2;
    const int t   = row & (LSEQ - 1);

    float4 v = *(const float4*)(X + (size_t)row * 128 + col);
    __nv_bfloat16 h0 = __float2bfloat16_rn(v.x), h1 = __float2bfloat16_rn(v.y);
    __nv_bfloat16 h2 = __float2bfloat16_rn(v.z), h3 = __float2bfloat16_rn(v.w);
    uint2 hh, ll;
    hh.x = ((uint32_t)__bfloat16_as_ushort(h1) << 16) | __bfloat16_as_ushort(h0);
    hh.y = ((uint32_t)__bfloat16_as_ushort(h3) << 16) | __bfloat16_as_ushort(h2);
    ll.x = pack_bf16(v.x - __bfloat162float(h0), v.y - __bfloat162float(h1));
    ll.y = pack_bf16(v.z - __bfloat162float(h2), v.w - __bfloat162float(h3));
    *(uint2*)(A1 + (size_t)row * 256 + col)       = hh;
    *(uint2*)(A1 + (size_t)row * 256 + 128 + col) = ll;

    const int starts[8] = {0, 2047, 4093, 6138, 8182, 10225, 12267, 14308};
    float4 s = make_float4(0.f, 0.f, 0.f, 0.f);
#pragma unroll
    for (int d = 1; d <= 8; ++d) {
        if (t >= d) {
            const float wd = __ldg(&ea[starts[d - 1]]);
            float4 xd = *(const float4*)(X + (size_t)(row - d) * 128 + col);
            s.x = fmaf(wd, xd.x, s.x); s.y = fmaf(wd, xd.y, s.y);
            s.z = fmaf(wd, xd.z, s.z); s.w = fmaf(wd, xd.w, s.w);
        }
    }
    uint2 so;
    so.x = pack_bf16(s.x, s.y);
    so.y = pack_bf16(s.z, s.w);
    *(uint2*)(SA + (size_t)row * 128 + col) = so;
}

// ---------------------------------------------------------------------------
// shift_h: SH[i,:] = sum_d w_d * Hh[i-d,:]   (Hh = hi half of [N, 512] layout)
// ---------------------------------------------------------------------------
__global__ void shift_h(const __nv_bfloat16* __restrict__ Hh, const float* __restrict__ ea,
                        __nv_bfloat16* __restrict__ SH)
{
    const int idx = blockIdx.x * blockDim.x + threadIdx.x;
    const int row = idx >> 6;
    const int col = (idx & 63) << 2;
    const int t   = row & (LSEQ - 1);

    const int starts[8] = {0, 2047, 4093, 6138, 8182, 10225, 12267, 14308};
    float4 s = make_float4(0.f, 0.f, 0.f, 0.f);
#pragma unroll
    for (int d = 1; d <= 8; ++d) {
        if (t >= d) {
            const float wd = __ldg(&ea[starts[d - 1]]);
            uint2 u = *(const uint2*)(Hh + (size_t)(row - d) * 512 + col);
            s.x = fmaf(wd, __bfloat162float(__ushort_as_bfloat16((ushort)(u.x & 0xFFFF))), s.x);
            s.y = fmaf(wd, __bfloat162float(__ushort_as_bfloat16((ushort)(u.x >> 16))),    s.y);
            s.z = fmaf(wd, __bfloat162float(__ushort_as_bfloat16((ushort)(u.y & 0xFFFF))), s.z);
            s.w = fmaf(wd, __bfloat162float(__ushort_as_bfloat16((ushort)(u.y >> 16))),    s.w);
        }
    }
    uint2 so;
    so.x = pack_bf16(s.x, s.y);
    so.y = pack_bf16(s.z, s.w);
    *(uint2*)(SH + (size_t)row * 256 + col) = so;
}

// ---------------------------------------------------------------------------
extern "C" void kernel_launch(void* const* d_in, const int* in_sizes, int n_in,
                              void* d_out, int out_size)
{
    const float* X       = (const float*)d_in[0];
    const float* W_rel1  = (const float*)d_in[1];
    const float* b_rel1  = (const float*)d_in[2];
    const float* W_root1 = (const float*)d_in[3];
    const float* W_rel2  = (const float*)d_in[4];
    const float* b_rel2  = (const float*)d_in[5];
    const float* W_root2 = (const float*)d_in[6];
    const float* a1      = (const float*)d_in[7];
    const float* a2      = (const float*)d_in[8];
    const float* W_fc    = (const float*)d_in[9];
    const float* b_fc    = (const float*)d_in[10];
    const float* ea      = (const float*)d_in[11];
    float*       out     = (float*)d_out;

    __nv_bfloat16 *A1, *A2, *A3, *SA, *SH, *B1s, *B2s, *Bfs;
    cudaGetSymbolAddress((void**)&A1,  g_A1);
    cudaGetSymbolAddress((void**)&A2,  g_A2);
    cudaGetSymbolAddress((void**)&A3,  g_A3);
    cudaGetSymbolAddress((void**)&SA,  g_SA);
    cudaGetSymbolAddress((void**)&SH,  g_SH);
    cudaGetSymbolAddress((void**)&B1s, g_B1s);
    cudaGetSymbolAddress((void**)&B2s, g_B2s);
    cudaGetSymbolAddress((void**)&Bfs, g_Bfs);

    constexpr int SMB = NSTG * STAGEB;   // 122880
    cudaFuncSetAttribute(gemm_mma<4, true>,  cudaFuncAttributeMaxDynamicSharedMemorySize, SMB);
    cudaFuncSetAttribute(gemm_mma<3, false>, cudaFuncAttributeMaxDynamicSharedMemorySize, SMB);

    // all prep in one launch
    prep_all<<<224 + NNODE * 32 / 256, 256>>>(X, ea, W_rel1, W_root1, W_rel2, W_root2, W_fc,
                                              B1s, B2s, Bfs, A1, SA);

    // Layer 1: H1 = prelu([S.X | Xh | Xh | Xl] @ [Wrel1h|Wroot1h|Wroot1l|Wroot1h]^T + b1)
    gemm_mma<4, true><<<dim3(2, 128), 256, SMB>>>(SA, A1, A1, A1 + 128,
                                                  128, 256, 256, 256,
                                                  B1s, b_rel1, a1, A2, 128, 512);
    // S.H1
    shift_h<<<NNODE * 64 / 256, 256>>>(A2, ea, SH);

    // Layer 2
    gemm_mma<4, true><<<dim3(2, 128), 256, SMB>>>(SH, A2, A2, A2 + 256,
                                                  256, 512, 512, 512,
                                                  B2s, b_rel2, a2, A3, 256, 512);
    // FC: out = [H2h|H2h|H2l] @ [Wfch|Wfcl|Wfch]^T + b_fc
    gemm_mma<3, false><<<dim3(1, 128), 256, SMB>>>(A3, A3, A3 + 256, A3,
                                                   512, 512, 512, 512,
                                                   Bfs, b_fc, nullptr, out, 256, 128);
}